// round 1
// baseline (speedup 1.0000x reference)
#include <cuda_runtime.h>

#define NN 100000
#define EE 600000
#define HH 128
#define AA 64
#define GG 64
#define LL 3
#define EPSN 1e-5f

// ---------------- scratch (device globals; no allocation allowed) ----------
__device__ float g_bufA[NN * HH];   // hW
__device__ float g_bufB[NN * HH];   // h (layer output)
__device__ float g_as[NN], g_ad[NN];
__device__ unsigned g_menc[NN];
__device__ float g_ssum[NN];
__device__ float g_ex[EE];
__device__ int g_src[EE], g_dst[EE];
__device__ int g_batch[NN];
__device__ float g_colsum[HH], g_colsq[HH];
__device__ float g_shift[HH], g_scale[HH], g_gb[HH];
__device__ float g_pool[GG * HH];
__device__ float g_z[GG * HH];
__device__ int g_edge_is32, g_batch_is32;

// ---------------- helpers ----------------
__device__ __forceinline__ unsigned fenc(float f) {
    unsigned u = __float_as_uint(f);
    return (u >> 31) ? ~u : (u | 0x80000000u);
}
__device__ __forceinline__ float fdec(unsigned u) {
    u = (u >> 31) ? (u & 0x7FFFFFFFu) : ~u;
    return __uint_as_float(u);
}
__device__ __forceinline__ float lrelu(float x, float a) { return x > 0.f ? x : a * x; }

// ---------------- dtype detection (int32 vs int64 inputs) ------------------
__global__ void k_detect(const void* eraw, const void* braw) {
    __shared__ int s_e, s_b;
    if (threadIdx.x == 0) { s_e = 0; s_b = 0; }
    __syncthreads();
    const long long* e64 = (const long long*)eraw;
    const long long* b64 = (const long long*)braw;
    int bad_e = 0, bad_b = 0;
    for (int i = threadIdx.x; i < 1024; i += blockDim.x) {
        long long v = e64[(long long)i * (EE / 1024)];
        if (v < 0 || v >= NN) bad_e = 1;
        long long bv = b64[(long long)i * ((NN / 2) / 1024)];
        if (bv < 0 || bv >= GG) bad_b = 1;
    }
    if (bad_e) atomicOr(&s_e, 1);
    if (bad_b) atomicOr(&s_b, 1);
    __syncthreads();
    if (threadIdx.x == 0) { g_edge_is32 = s_e; g_batch_is32 = s_b; }
}

__global__ void k_cvt(const void* eraw, const void* braw) {
    int i = blockIdx.x * blockDim.x + threadIdx.x;
    if (i < EE) {
        if (g_edge_is32) {
            const int* p = (const int*)eraw;
            g_src[i] = p[i]; g_dst[i] = p[EE + i];
        } else {
            const long long* p = (const long long*)eraw;
            g_src[i] = (int)p[i]; g_dst[i] = (int)p[EE + i];
        }
    }
    if (i < NN) {
        if (g_batch_is32) g_batch[i] = ((const int*)braw)[i];
        else              g_batch[i] = (int)((const long long*)braw)[i];
    }
}

// ---------------- GEMM: Y[N,128] = X[N,128] @ W[128,128] -------------------
// 256 threads/block, 64 rows/block, 4x8 register tile per thread.
#define GEMM_ROWS 64
#define XP 132
__global__ void k_gemm(const float* __restrict__ X, const float* __restrict__ W,
                       float* __restrict__ Y) {
    extern __shared__ float sm[];
    float* sW = sm;               // 128*128
    float* sX = sm + 128 * 128;   // 64*XP
    int row0 = blockIdx.x * GEMM_ROWS;
    int tid = threadIdx.x;
    // load W (16384 floats = 4096 float4)
    #pragma unroll
    for (int it = 0; it < 16; ++it) {
        int idx = it * 256 + tid;
        ((float4*)sW)[idx] = ((const float4*)W)[idx];
    }
    // load X tile (64 rows x 128), pad OOB with zero
    int nrows = NN - row0; if (nrows > GEMM_ROWS) nrows = GEMM_ROWS;
    #pragma unroll
    for (int it = 0; it < 8; ++it) {
        int idx = it * 256 + tid;        // float4 idx, 32 per row
        int r = idx >> 5;
        int k4 = idx & 31;
        float4 v = make_float4(0.f, 0.f, 0.f, 0.f);
        if (r < nrows) v = ((const float4*)(X + (long long)(row0 + r) * HH))[k4];
        float* d = sX + r * XP + k4 * 4;
        d[0] = v.x; d[1] = v.y; d[2] = v.z; d[3] = v.w;
    }
    __syncthreads();
    int tc = tid & 15;     // col group: cols tc*8 .. tc*8+7
    int tr = tid >> 4;     // row group: rows tr*4 .. tr*4+3
    float acc[4][8];
    #pragma unroll
    for (int i = 0; i < 4; i++)
        #pragma unroll
        for (int j = 0; j < 8; j++) acc[i][j] = 0.f;
    const float* xb = sX + (tr * 4) * XP;
    #pragma unroll 4
    for (int k = 0; k < 128; k++) {
        float xv[4];
        xv[0] = xb[k]; xv[1] = xb[XP + k]; xv[2] = xb[2 * XP + k]; xv[3] = xb[3 * XP + k];
        float4 wa = *(const float4*)(sW + k * 128 + tc * 8);
        float4 wb = *(const float4*)(sW + k * 128 + tc * 8 + 4);
        float wv[8] = {wa.x, wa.y, wa.z, wa.w, wb.x, wb.y, wb.z, wb.w};
        #pragma unroll
        for (int i = 0; i < 4; i++)
            #pragma unroll
            for (int j = 0; j < 8; j++) acc[i][j] += xv[i] * wv[j];
    }
    #pragma unroll
    for (int i = 0; i < 4; i++) {
        int r = row0 + tr * 4 + i;
        if (r < NN) {
            float4 o0 = make_float4(acc[i][0], acc[i][1], acc[i][2], acc[i][3]);
            float4 o1 = make_float4(acc[i][4], acc[i][5], acc[i][6], acc[i][7]);
            float4* yp = (float4*)(Y + (long long)r * HH + tc * 8);
            yp[0] = o0; yp[1] = o1;
        }
    }
}

// ---------------- attention logits per node --------------------------------
__global__ void k_att(const float* __restrict__ hW, const float* __restrict__ asrc,
                      const float* __restrict__ adst) {
    int warp = (blockIdx.x * blockDim.x + threadIdx.x) >> 5;
    int lane = threadIdx.x & 31;
    if (warp >= NN) return;
    float4 v = ((const float4*)(hW + (long long)warp * HH))[lane];
    float4 s4 = ((const float4*)asrc)[lane];
    float4 d4 = ((const float4*)adst)[lane];
    float ss = v.x * s4.x + v.y * s4.y + v.z * s4.z + v.w * s4.w;
    float dd = v.x * d4.x + v.y * d4.y + v.z * d4.z + v.w * d4.w;
    #pragma unroll
    for (int o = 16; o; o >>= 1) {
        ss += __shfl_xor_sync(0xFFFFFFFFu, ss, o);
        dd += __shfl_xor_sync(0xFFFFFFFFu, dd, o);
    }
    if (lane == 0) { g_as[warp] = ss; g_ad[warp] = dd; }
}

__global__ void k_init_nodes() {
    int i = blockIdx.x * blockDim.x + threadIdx.x;
    if (i < NN) { g_menc[i] = 0u; g_ssum[i] = 0.f; }
}

__global__ void k_edge_max() {
    int e = blockIdx.x * blockDim.x + threadIdx.x;
    if (e >= EE) return;
    int s = g_src[e], d = g_dst[e];
    float x = lrelu(g_as[s] + g_ad[d], 0.2f);
    atomicMax(&g_menc[d], fenc(x));
}

__global__ void k_edge_exp() {
    int e = blockIdx.x * blockDim.x + threadIdx.x;
    if (e >= EE) return;
    int s = g_src[e], d = g_dst[e];
    float x = lrelu(g_as[s] + g_ad[d], 0.2f);
    float m = fdec(g_menc[d]);
    float ex = __expf(x - m);
    g_ex[e] = ex;
    atomicAdd(&g_ssum[d], ex);
}

__global__ void k_init_h(float* __restrict__ h, const float* __restrict__ bias) {
    int i = blockIdx.x * blockDim.x + threadIdx.x;   // float4 index over N*32
    if (i >= NN * 32) return;
    int c4 = i & 31;
    ((float4*)h)[i] = ((const float4*)bias)[c4];
}

__global__ void k_scatter(const float* __restrict__ hW, float* __restrict__ hout) {
    int e = (blockIdx.x * blockDim.x + threadIdx.x) >> 5;
    int lane = threadIdx.x & 31;
    if (e >= EE) return;
    int s = g_src[e], d = g_dst[e];
    float alpha = g_ex[e] / (g_ssum[d] + 1e-16f);
    float4 v = ((const float4*)(hW + (long long)s * HH))[lane];
    v.x *= alpha; v.y *= alpha; v.z *= alpha; v.w *= alpha;
    float* p = hout + (long long)d * HH + lane * 4;
    asm volatile("red.global.add.v4.f32 [%0], {%1,%2,%3,%4};"
                 :: "l"(p), "f"(v.x), "f"(v.y), "f"(v.z), "f"(v.w) : "memory");
}

// ---------------- GraphNorm -------------------------------------------------
__global__ void k_zero_stats() {
    int c = threadIdx.x;
    if (c < HH) { g_colsum[c] = 0.f; g_colsq[c] = 0.f; }
}

__global__ void k_colstats(const float* __restrict__ h) {
    int c = threadIdx.x;   // 128 threads
    float sum = 0.f, sq = 0.f;
    for (int r = blockIdx.x; r < NN; r += gridDim.x) {
        float v = h[(long long)r * HH + c];
        sum += v; sq += v * v;
    }
    atomicAdd(&g_colsum[c], sum);
    atomicAdd(&g_colsq[c], sq);
}

__global__ void k_norm_prep(const float* __restrict__ w, const float* __restrict__ b,
                            const float* __restrict__ ms) {
    int c = threadIdx.x;
    if (c >= HH) return;
    float invN = 1.0f / (float)NN;
    float mean = g_colsum[c] * invN;
    float ex2 = g_colsq[c] * invN;
    float s = ms[c];
    float var = ex2 - 2.f * s * mean * mean + s * s * mean * mean;
    g_shift[c] = mean * s;
    g_scale[c] = w[c] * rsqrtf(var + EPSN);
    g_gb[c] = b[c];
}

__global__ void k_norm_apply(float* __restrict__ h) {
    int i = blockIdx.x * blockDim.x + threadIdx.x;  // float4 index
    if (i >= NN * 32) return;
    int c4 = i & 31;
    float4 v = ((float4*)h)[i];
    float4 sh = ((const float4*)g_shift)[c4];
    float4 sc = ((const float4*)g_scale)[c4];
    float4 bb = ((const float4*)g_gb)[c4];
    v.x = lrelu((v.x - sh.x) * sc.x + bb.x, 0.01f);
    v.y = lrelu((v.y - sh.y) * sc.y + bb.y, 0.01f);
    v.z = lrelu((v.z - sh.z) * sc.z + bb.z, 0.01f);
    v.w = lrelu((v.w - sh.w) * sc.w + bb.w, 0.01f);
    ((float4*)h)[i] = v;
}

// ---------------- pooling + MLP ---------------------------------------------
__global__ void k_zero_pool() {
    int i = blockIdx.x * blockDim.x + threadIdx.x;
    if (i < GG * HH) g_pool[i] = 0.f;
}

__global__ void k_pool(const float* __restrict__ h) {
    int i = blockIdx.x * blockDim.x + threadIdx.x;   // over N*128
    if (i >= NN * HH) return;
    int r = i >> 7, c = i & 127;
    atomicAdd(&g_pool[g_batch[r] * HH + c], h[i]);
}

__global__ void k_mlp1(const float* __restrict__ W1, const float* __restrict__ b1) {
    __shared__ float sp[HH];
    int g = blockIdx.x, c = threadIdx.x;
    sp[c] = g_pool[g * HH + c];
    __syncthreads();
    float acc = b1[c];
    #pragma unroll 4
    for (int k = 0; k < HH; k++) acc += sp[k] * W1[k * HH + c];
    g_z[g * HH + c] = lrelu(acc, 0.01f);
}

__global__ void k_mlp2(const float* __restrict__ W2, const float* __restrict__ b2,
                       float* __restrict__ out) {
    __shared__ float sz[HH];
    int g = blockIdx.x, a = threadIdx.x;   // 64 threads
    sz[a] = g_z[g * HH + a];
    sz[a + 64] = g_z[g * HH + a + 64];
    __syncthreads();
    float acc = b2[a];
    #pragma unroll 4
    for (int k = 0; k < HH; k++) acc += sz[k] * W2[k * AA + a];
    out[g * AA + a] = acc;
}

// ---------------- launcher ---------------------------------------------------
extern "C" void kernel_launch(void* const* d_in, const int* in_sizes, int n_in,
                              void* d_out, int out_size) {
    const float* x        = (const float*)d_in[0];
    const void*  e_raw    = d_in[1];
    const void*  b_raw    = d_in[2];
    const float* Ws       = (const float*)d_in[3];
    const float* att_src  = (const float*)d_in[4];
    const float* att_dst  = (const float*)d_in[5];
    const float* conv_bias= (const float*)d_in[6];
    const float* gn_w     = (const float*)d_in[7];
    const float* gn_b     = (const float*)d_in[8];
    const float* gn_ms    = (const float*)d_in[9];
    const float* W1       = (const float*)d_in[10];
    const float* b1       = (const float*)d_in[11];
    const float* W2       = (const float*)d_in[12];
    const float* b2       = (const float*)d_in[13];

    float* bufA; float* bufB;
    cudaGetSymbolAddress((void**)&bufA, g_bufA);
    cudaGetSymbolAddress((void**)&bufB, g_bufB);

    const int gemm_smem = (128 * 128 + GEMM_ROWS * XP) * sizeof(float);
    cudaFuncSetAttribute(k_gemm, cudaFuncAttributeMaxDynamicSharedMemorySize, gemm_smem);

    k_detect<<<1, 256>>>(e_raw, b_raw);
    k_cvt<<<(EE + 255) / 256, 256>>>(e_raw, b_raw);

    const int gemm_grid = (NN + GEMM_ROWS - 1) / GEMM_ROWS;
    const int eg = (EE + 255) / 256;
    const int ng = (NN + 255) / 256;
    const int nh4 = (NN * 32 + 255) / 256;

    for (int l = 0; l < LL; l++) {
        const float* hin = (l == 0) ? x : bufB;
        k_gemm<<<gemm_grid, 256, gemm_smem>>>(hin, Ws + l * HH * HH, bufA);
        k_att<<<(NN * 32 + 255) / 256, 256>>>(bufA, att_src + l * HH, att_dst + l * HH);
        k_init_nodes<<<ng, 256>>>();
        k_edge_max<<<eg, 256>>>();
        k_edge_exp<<<eg, 256>>>();
        k_init_h<<<nh4, 256>>>(bufB, conv_bias + l * HH);
        k_scatter<<<(EE * 32 + 255) / 256, 256>>>(bufA, bufB);
        if (l < LL - 1) {
            k_zero_stats<<<1, 128>>>();
            k_colstats<<<512, 128>>>(bufB);
            k_norm_prep<<<1, 128>>>(gn_w + l * HH, gn_b + l * HH, gn_ms + l * HH);
            k_norm_apply<<<nh4, 256>>>(bufB);
        }
    }

    k_zero_pool<<<(GG * HH + 255) / 256, 256>>>();
    k_pool<<<(NN * HH + 255) / 256, 256>>>(bufB);
    k_mlp1<<<GG, 128>>>(W1, b1);
    k_mlp2<<<GG, 64>>>(W2, b2, (float*)d_out);
}

// round 2
// speedup vs baseline: 1.2132x; 1.2132x over previous
#include <cuda_runtime.h>

#define NN 100000
#define EE 600000
#define HH 128
#define AA 64
#define GG 64
#define LL 3
#define EPSN 1e-5f

// ---------------- scratch (device globals; no allocation allowed) ----------
__device__ float g_bufA[NN * HH];   // hW
__device__ float g_bufB[NN * HH];   // h (layer output)
__device__ float g_as[NN], g_ad[NN];
__device__ int g_src[EE], g_dst[EE];
__device__ int g_batch[NN];
__device__ int g_deg[NN];
__device__ int g_rowstart[NN + 1];
__device__ int g_cursor[NN];
__device__ int g_ssrc[EE];          // src ids grouped by dst
__device__ int g_bsum[128], g_boff[128];
__device__ float g_colsum[HH], g_colsq[HH];
__device__ float g_shift[HH], g_scale[HH], g_gb[HH];
__device__ float g_pool[GG * HH];
__device__ float g_z[GG * HH];
__device__ int g_edge_is32, g_batch_is32;

__device__ __forceinline__ float lrelu(float x, float a) { return x > 0.f ? x : a * x; }

// ---------------- dtype detection (int32 vs int64 inputs) ------------------
__global__ void k_detect(const void* eraw, const void* braw) {
    __shared__ int s_e, s_b;
    if (threadIdx.x == 0) { s_e = 0; s_b = 0; }
    __syncthreads();
    const long long* e64 = (const long long*)eraw;
    const long long* b64 = (const long long*)braw;
    int bad_e = 0, bad_b = 0;
    for (int i = threadIdx.x; i < 1024; i += blockDim.x) {
        long long v = e64[(long long)i * (EE / 1024)];
        if (v < 0 || v >= NN) bad_e = 1;
        long long bv = b64[(long long)i * ((NN / 2) / 1024)];
        if (bv < 0 || bv >= GG) bad_b = 1;
    }
    if (bad_e) atomicOr(&s_e, 1);
    if (bad_b) atomicOr(&s_b, 1);
    __syncthreads();
    if (threadIdx.x == 0) { g_edge_is32 = s_e; g_batch_is32 = s_b; }
}

__global__ void k_cvt(const void* eraw, const void* braw) {
    int i = blockIdx.x * blockDim.x + threadIdx.x;
    if (i < EE) {
        if (g_edge_is32) {
            const int* p = (const int*)eraw;
            g_src[i] = p[i]; g_dst[i] = p[EE + i];
        } else {
            const long long* p = (const long long*)eraw;
            g_src[i] = (int)p[i]; g_dst[i] = (int)p[EE + i];
        }
    }
    if (i < NN) {
        if (g_batch_is32) g_batch[i] = ((const int*)braw)[i];
        else              g_batch[i] = (int)((const long long*)braw)[i];
        g_deg[i] = 0;
    }
    if (i < GG * HH) g_pool[i] = 0.f;
}

// ---------------- CSR build -------------------------------------------------
__global__ void k_hist() {
    int e = blockIdx.x * blockDim.x + threadIdx.x;
    if (e < EE) atomicAdd(&g_deg[g_dst[e]], 1);
}

// blocks of 1024 elems (4/thread, 256 threads)
__global__ void k_scan1() {
    __shared__ int s_w[8];
    int b = blockIdx.x, t = threadIdx.x;
    int base = b * 1024 + t * 4;
    int d[4];
    #pragma unroll
    for (int i = 0; i < 4; i++) d[i] = (base + i < NN) ? g_deg[base + i] : 0;
    int local = d[0] + d[1] + d[2] + d[3];
    int lane = t & 31, w = t >> 5;
    int v = local;
    #pragma unroll
    for (int o = 1; o < 32; o <<= 1) {
        int u = __shfl_up_sync(0xFFFFFFFFu, v, o);
        if (lane >= o) v += u;
    }
    if (lane == 31) s_w[w] = v;
    __syncthreads();
    if (t < 8) {
        int x = s_w[t];
        #pragma unroll
        for (int o = 1; o < 8; o <<= 1) {
            int u = __shfl_up_sync(0xFFu, x, o);
            if (t >= o) x += u;
        }
        s_w[t] = x;
    }
    __syncthreads();
    int warpoff = (w > 0) ? s_w[w - 1] : 0;
    int excl = warpoff + v - local;
    #pragma unroll
    for (int i = 0; i < 4; i++) {
        if (base + i < NN) g_rowstart[base + i] = excl;
        excl += d[i];
    }
    if (t == 0) g_bsum[b] = s_w[7];
}

__global__ void k_scan2() {   // 1 block, 128 threads
    __shared__ int sb[128];
    int t = threadIdx.x;
    int NB = (NN + 1023) / 1024;
    sb[t] = (t < NB) ? g_bsum[t] : 0;
    __syncthreads();
    for (int o = 1; o < 128; o <<= 1) {
        int u = (t >= o) ? sb[t - o] : 0;
        __syncthreads();
        sb[t] += u;
        __syncthreads();
    }
    g_boff[t] = (t > 0) ? sb[t - 1] : 0;
}

__global__ void k_scan3() {
    int i = blockIdx.x * blockDim.x + threadIdx.x;
    if (i < NN) {
        int v = g_rowstart[i] + g_boff[i >> 10];
        g_rowstart[i] = v;
        g_cursor[i] = v;
    }
    if (i == 0) g_rowstart[NN] = EE;
}

__global__ void k_fill() {
    int e = blockIdx.x * blockDim.x + threadIdx.x;
    if (e >= EE) return;
    int d = g_dst[e];
    int slot = atomicAdd(&g_cursor[d], 1);
    g_ssrc[slot] = g_src[e];
}

// ---------------- GEMM: Y = X @ W, fused norm-on-load + attention epilogue --
#define GEMM_ROWS 64
#define XP 132
__global__ void k_gemm(const float* __restrict__ X, const float* __restrict__ W,
                       float* __restrict__ Y,
                       const float* __restrict__ avs, const float* __restrict__ avd,
                       int donorm) {
    extern __shared__ float sm[];
    float* sW = sm;               // 128*128
    float* sX = sm + 128 * 128;   // 64*XP
    int row0 = blockIdx.x * GEMM_ROWS;
    int tid = threadIdx.x;
    #pragma unroll
    for (int it = 0; it < 16; ++it) {
        int idx = it * 256 + tid;
        ((float4*)sW)[idx] = ((const float4*)W)[idx];
    }
    int nrows = NN - row0; if (nrows > GEMM_ROWS) nrows = GEMM_ROWS;
    #pragma unroll
    for (int it = 0; it < 8; ++it) {
        int idx = it * 256 + tid;        // float4 idx, 32 per row
        int r = idx >> 5;
        int k4 = idx & 31;
        float4 v = make_float4(0.f, 0.f, 0.f, 0.f);
        if (r < nrows) {
            v = ((const float4*)(X + (long long)(row0 + r) * HH))[k4];
            if (donorm) {
                float4 sh = ((const float4*)g_shift)[k4];
                float4 sc = ((const float4*)g_scale)[k4];
                float4 bb = ((const float4*)g_gb)[k4];
                v.x = lrelu((v.x - sh.x) * sc.x + bb.x, 0.01f);
                v.y = lrelu((v.y - sh.y) * sc.y + bb.y, 0.01f);
                v.z = lrelu((v.z - sh.z) * sc.z + bb.z, 0.01f);
                v.w = lrelu((v.w - sh.w) * sc.w + bb.w, 0.01f);
            }
        }
        float* d = sX + r * XP + k4 * 4;
        d[0] = v.x; d[1] = v.y; d[2] = v.z; d[3] = v.w;
    }
    __syncthreads();
    int tc = tid & 15;
    int tr = tid >> 4;
    float acc[4][8];
    #pragma unroll
    for (int i = 0; i < 4; i++)
        #pragma unroll
        for (int j = 0; j < 8; j++) acc[i][j] = 0.f;
    const float* xb = sX + (tr * 4) * XP;
    #pragma unroll 4
    for (int k = 0; k < 128; k++) {
        float xv[4];
        xv[0] = xb[k]; xv[1] = xb[XP + k]; xv[2] = xb[2 * XP + k]; xv[3] = xb[3 * XP + k];
        float4 wa = *(const float4*)(sW + k * 128 + tc * 8);
        float4 wb = *(const float4*)(sW + k * 128 + tc * 8 + 4);
        float wv[8] = {wa.x, wa.y, wa.z, wa.w, wb.x, wb.y, wb.z, wb.w};
        #pragma unroll
        for (int i = 0; i < 4; i++)
            #pragma unroll
            for (int j = 0; j < 8; j++) acc[i][j] += xv[i] * wv[j];
    }
    #pragma unroll
    for (int i = 0; i < 4; i++) {
        int r = row0 + tr * 4 + i;
        if (r < NN) {
            float4 o0 = make_float4(acc[i][0], acc[i][1], acc[i][2], acc[i][3]);
            float4 o1 = make_float4(acc[i][4], acc[i][5], acc[i][6], acc[i][7]);
            float4* yp = (float4*)(Y + (long long)r * HH + tc * 8);
            yp[0] = o0; yp[1] = o1;
        }
    }
    // ---- attention epilogue: g_as[r] = hW[r]·avs, g_ad[r] = hW[r]·avd ----
    float av_s[8], av_d[8];
    #pragma unroll
    for (int j = 0; j < 8; j++) { av_s[j] = avs[tc * 8 + j]; av_d[j] = avd[tc * 8 + j]; }
    float ps[4], pd[4];
    #pragma unroll
    for (int i = 0; i < 4; i++) {
        float a = 0.f, b = 0.f;
        #pragma unroll
        for (int j = 0; j < 8; j++) { a += acc[i][j] * av_s[j]; b += acc[i][j] * av_d[j]; }
        ps[i] = a; pd[i] = b;
    }
    #pragma unroll
    for (int o = 1; o < 16; o <<= 1) {
        #pragma unroll
        for (int i = 0; i < 4; i++) {
            ps[i] += __shfl_xor_sync(0xFFFFFFFFu, ps[i], o);
            pd[i] += __shfl_xor_sync(0xFFFFFFFFu, pd[i], o);
        }
    }
    if (tc == 0) {
        #pragma unroll
        for (int i = 0; i < 4; i++) {
            int r = row0 + tr * 4 + i;
            if (r < NN) { g_as[r] = ps[i]; g_ad[r] = pd[i]; }
        }
    }
}

// ---------------- GAT aggregation: per-dst-node warp, CSR --------------------
__global__ void k_gat_agg(const float* __restrict__ hW, float* __restrict__ hout,
                          const float* __restrict__ bias) {
    int node = (blockIdx.x * blockDim.x + threadIdx.x) >> 5;
    int lane = threadIdx.x & 31;
    if (node >= NN) return;
    int rs = g_rowstart[node], re = g_rowstart[node + 1];
    float ad_d = g_ad[node];
    // pass 1: online softmax stats over incoming edges (lane-parallel)
    float m = -1e30f, s = 0.f;
    for (int i = rs + lane; i < re; i += 32) {
        int src = g_ssrc[i];
        float x = lrelu(g_as[src] + ad_d, 0.2f);
        if (x > m) { s = s * __expf(m - x) + 1.f; m = x; }
        else       { s += __expf(x - m); }
    }
    #pragma unroll
    for (int o = 16; o; o >>= 1) {
        float om = __shfl_xor_sync(0xFFFFFFFFu, m, o);
        float os = __shfl_xor_sync(0xFFFFFFFFu, s, o);
        float nm = fmaxf(m, om);
        s = s * __expf(m - nm) + os * __expf(om - nm);
        m = nm;
    }
    float4 bb = ((const float4*)bias)[lane];
    float4 acc = bb;
    if (re > rs) {
        float inv = 1.f / (s + 1e-16f);
        for (int i = rs; i < re; ++i) {
            int src = g_ssrc[i];
            float alpha = __expf(lrelu(g_as[src] + ad_d, 0.2f) - m) * inv;
            float4 v = ((const float4*)(hW + (long long)src * HH))[lane];
            acc.x += alpha * v.x; acc.y += alpha * v.y;
            acc.z += alpha * v.z; acc.w += alpha * v.w;
        }
    }
    ((float4*)(hout + (long long)node * HH))[lane] = acc;
}

// ---------------- GraphNorm -------------------------------------------------
__global__ void k_zero_stats() {
    int c = threadIdx.x;
    if (c < HH) { g_colsum[c] = 0.f; g_colsq[c] = 0.f; }
}

__global__ void k_colstats(const float* __restrict__ h) {
    int c = threadIdx.x;   // 128 threads
    float sum = 0.f, sq = 0.f;
    for (int r = blockIdx.x; r < NN; r += gridDim.x) {
        float v = h[(long long)r * HH + c];
        sum += v; sq += v * v;
    }
    atomicAdd(&g_colsum[c], sum);
    atomicAdd(&g_colsq[c], sq);
}

__global__ void k_norm_prep(const float* __restrict__ w, const float* __restrict__ b,
                            const float* __restrict__ ms) {
    int c = threadIdx.x;
    if (c >= HH) return;
    float invN = 1.0f / (float)NN;
    float mean = g_colsum[c] * invN;
    float ex2 = g_colsq[c] * invN;
    float s = ms[c];
    float var = ex2 - 2.f * s * mean * mean + s * s * mean * mean;
    g_shift[c] = mean * s;
    g_scale[c] = w[c] * rsqrtf(var + EPSN);
    g_gb[c] = b[c];
}

// ---------------- pooling (batch is sorted) + MLP ---------------------------
#define PCH 256
__global__ void k_pool2(const float* __restrict__ h) {
    int c = threadIdx.x;               // 128 threads = one column each
    int r0 = blockIdx.x * PCH;
    int rend = r0 + PCH; if (rend > NN) rend = NN;
    if (r0 >= NN) return;
    int cur = g_batch[r0];
    float acc = 0.f;
    for (int r = r0; r < rend; r++) {
        int b = g_batch[r];
        if (b != cur) { atomicAdd(&g_pool[cur * HH + c], acc); acc = 0.f; cur = b; }
        acc += h[(long long)r * HH + c];
    }
    atomicAdd(&g_pool[cur * HH + c], acc);
}

__global__ void k_mlp1(const float* __restrict__ W1, const float* __restrict__ b1) {
    __shared__ float sp[HH];
    int g = blockIdx.x, c = threadIdx.x;
    sp[c] = g_pool[g * HH + c];
    __syncthreads();
    float acc = b1[c];
    #pragma unroll 4
    for (int k = 0; k < HH; k++) acc += sp[k] * W1[k * HH + c];
    g_z[g * HH + c] = lrelu(acc, 0.01f);
}

__global__ void k_mlp2(const float* __restrict__ W2, const float* __restrict__ b2,
                       float* __restrict__ out) {
    __shared__ float sz[HH];
    int g = blockIdx.x, a = threadIdx.x;   // 64 threads
    sz[a] = g_z[g * HH + a];
    sz[a + 64] = g_z[g * HH + a + 64];
    __syncthreads();
    float acc = b2[a];
    #pragma unroll 4
    for (int k = 0; k < HH; k++) acc += sz[k] * W2[k * AA + a];
    out[g * AA + a] = acc;
}

// ---------------- launcher ---------------------------------------------------
extern "C" void kernel_launch(void* const* d_in, const int* in_sizes, int n_in,
                              void* d_out, int out_size) {
    const float* x        = (const float*)d_in[0];
    const void*  e_raw    = d_in[1];
    const void*  b_raw    = d_in[2];
    const float* Ws       = (const float*)d_in[3];
    const float* att_src  = (const float*)d_in[4];
    const float* att_dst  = (const float*)d_in[5];
    const float* conv_bias= (const float*)d_in[6];
    const float* gn_w     = (const float*)d_in[7];
    const float* gn_b     = (const float*)d_in[8];
    const float* gn_ms    = (const float*)d_in[9];
    const float* W1       = (const float*)d_in[10];
    const float* b1       = (const float*)d_in[11];
    const float* W2       = (const float*)d_in[12];
    const float* b2       = (const float*)d_in[13];

    float* bufA; float* bufB;
    cudaGetSymbolAddress((void**)&bufA, g_bufA);
    cudaGetSymbolAddress((void**)&bufB, g_bufB);

    const int gemm_smem = (128 * 128 + GEMM_ROWS * XP) * sizeof(float);
    cudaFuncSetAttribute(k_gemm, cudaFuncAttributeMaxDynamicSharedMemorySize, gemm_smem);

    const int eg = (EE + 255) / 256;
    const int ng = (NN + 255) / 256;
    const int NB = (NN + 1023) / 1024;

    k_detect<<<1, 256>>>(e_raw, b_raw);
    k_cvt<<<eg, 256>>>(e_raw, b_raw);
    k_hist<<<eg, 256>>>();
    k_scan1<<<NB, 256>>>();
    k_scan2<<<1, 128>>>();
    k_scan3<<<ng, 256>>>();
    k_fill<<<eg, 256>>>();

    const int gemm_grid = (NN + GEMM_ROWS - 1) / GEMM_ROWS;
    const int agg_grid = (NN * 32 + 255) / 256;

    for (int l = 0; l < LL; l++) {
        const float* hin = (l == 0) ? x : bufB;
        k_gemm<<<gemm_grid, 256, gemm_smem>>>(hin, Ws + l * HH * HH, bufA,
                                              att_src + l * HH, att_dst + l * HH,
                                              l > 0 ? 1 : 0);
        k_gat_agg<<<agg_grid, 256>>>(bufA, bufB, conv_bias + l * HH);
        if (l < LL - 1) {
            k_zero_stats<<<1, 128>>>();
            k_colstats<<<512, 128>>>(bufB);
            k_norm_prep<<<1, 128>>>(gn_w + l * HH, gn_b + l * HH, gn_ms + l * HH);
        }
    }

    k_pool2<<<(NN + PCH - 1) / PCH, 128>>>(bufB);
    k_mlp1<<<GG, 128>>>(W1, b1);
    k_mlp2<<<GG, 64>>>(W2, b2, (float*)d_out);
}

// round 4
// speedup vs baseline: 1.3908x; 1.1464x over previous
#include <cuda_runtime.h>
#include <cuda_bf16.h>
#include <cstdint>

#define NN 100000
#define EE 600000
#define HH 128
#define AA 64
#define GG 64
#define LL 3
#define EPSN 1e-5f
#define NTILES 782          // ceil(100000/128)
#define ASTRIDE 264         // padded bf16 cols (K=256 + 8 pad) -> conflict-free ldmatrix
#define IMG_ELEMS (HH * ASTRIDE)      // per-layer W image elements

// ---------------- scratch (device globals) ----------------------------------
__device__ float g_bufA[NN * HH];
__device__ float g_bufB[NN * HH];
__device__ float g_as[NN], g_ad[NN];
__device__ int g_src[EE], g_dst[EE];
__device__ int g_batch[NN];
__device__ int g_deg[NN];
__device__ int g_rowstart[NN + 1];
__device__ int g_cursor[NN];
__device__ int g_ssrc[EE];
__device__ int g_bsum[128], g_boff[128];
__device__ float g_colsum[HH], g_colsq[HH];
__device__ float g_shift[HH], g_scale[HH], g_gb[HH];
__device__ float g_pool[GG * HH];
__device__ float g_z[GG * HH];
__device__ int g_edge_is32, g_batch_is32;
__device__ __align__(16) __nv_bfloat16 g_Wimg[LL * IMG_ELEMS];  // Wt[n][k]: [Wh | Wl], padded

__device__ __forceinline__ float lrelu(float x, float a) { return x > 0.f ? x : a * x; }

__device__ __forceinline__ uint32_t smem_u32(const void* p) {
    uint32_t a;
    asm("{ .reg .u64 t; cvta.to.shared.u64 t, %1; cvt.u32.u64 %0, t; }" : "=r"(a) : "l"(p));
    return a;
}
__device__ __forceinline__ void ldm_x4(uint32_t* r, uint32_t addr) {
    asm volatile("ldmatrix.sync.aligned.m8n8.x4.shared.b16 {%0,%1,%2,%3}, [%4];"
                 : "=r"(r[0]), "=r"(r[1]), "=r"(r[2]), "=r"(r[3]) : "r"(addr));
}
__device__ __forceinline__ void mma16816(float* c, const uint32_t* a, const uint32_t* b) {
    asm volatile("mma.sync.aligned.m16n8k16.row.col.f32.bf16.bf16.f32 "
                 "{%0,%1,%2,%3}, {%4,%5,%6,%7}, {%8,%9}, {%0,%1,%2,%3};"
                 : "+f"(c[0]), "+f"(c[1]), "+f"(c[2]), "+f"(c[3])
                 : "r"(a[0]), "r"(a[1]), "r"(a[2]), "r"(a[3]), "r"(b[0]), "r"(b[1]));
}

// ---------------- dtype detection ------------------------------------------
__global__ void k_detect(const void* eraw, const void* braw) {
    __shared__ int s_e, s_b;
    if (threadIdx.x == 0) { s_e = 0; s_b = 0; }
    __syncthreads();
    const long long* e64 = (const long long*)eraw;
    const long long* b64 = (const long long*)braw;
    int bad_e = 0, bad_b = 0;
    for (int i = threadIdx.x; i < 1024; i += blockDim.x) {
        long long v = e64[(long long)i * (EE / 1024)];
        if (v < 0 || v >= NN) bad_e = 1;
        long long bv = b64[(long long)i * ((NN / 2) / 1024)];
        if (bv < 0 || bv >= GG) bad_b = 1;
    }
    if (bad_e) atomicOr(&s_e, 1);
    if (bad_b) atomicOr(&s_b, 1);
    __syncthreads();
    if (threadIdx.x == 0) { g_edge_is32 = s_e; g_batch_is32 = s_b; }
}

__global__ void k_cvt(const void* eraw, const void* braw) {
    int i = blockIdx.x * blockDim.x + threadIdx.x;
    if (i < EE) {
        if (g_edge_is32) {
            const int* p = (const int*)eraw;
            g_src[i] = p[i]; g_dst[i] = p[EE + i];
        } else {
            const long long* p = (const long long*)eraw;
            g_src[i] = (int)p[i]; g_dst[i] = (int)p[EE + i];
        }
    }
    if (i < NN) {
        if (g_batch_is32) g_batch[i] = ((const int*)braw)[i];
        else              g_batch[i] = (int)((const long long*)braw)[i];
        g_deg[i] = 0;
    }
    if (i < GG * HH) g_pool[i] = 0.f;
}

// ---------------- W prep: Wt[n][k] bf16 split, padded stride -----------------
__global__ void k_prepW(const float* __restrict__ Ws) {
    int i = blockIdx.x * blockDim.x + threadIdx.x;   // over LL*128*128
    if (i >= LL * HH * HH) return;
    int l = i / (HH * HH);
    int r = i - l * HH * HH;
    int k = r >> 7;          // W row (K dim)
    int n = r & 127;         // W col (N dim)
    float w = Ws[i];
    __nv_bfloat16 hi = __float2bfloat16_rn(w);
    float resid = w - __bfloat162float(hi);
    __nv_bfloat16 lo = __float2bfloat16_rn(resid);
    __nv_bfloat16* img = g_Wimg + (long long)l * IMG_ELEMS;
    img[n * ASTRIDE + k] = hi;
    img[n * ASTRIDE + 128 + k] = lo;
}

// ---------------- CSR build -------------------------------------------------
__global__ void k_hist() {
    int e = blockIdx.x * blockDim.x + threadIdx.x;
    if (e < EE) atomicAdd(&g_deg[g_dst[e]], 1);
}

__global__ void k_scan1() {
    __shared__ int s_w[8];
    int b = blockIdx.x, t = threadIdx.x;
    int base = b * 1024 + t * 4;
    int d[4];
    #pragma unroll
    for (int i = 0; i < 4; i++) d[i] = (base + i < NN) ? g_deg[base + i] : 0;
    int local = d[0] + d[1] + d[2] + d[3];
    int lane = t & 31, w = t >> 5;
    int v = local;
    #pragma unroll
    for (int o = 1; o < 32; o <<= 1) {
        int u = __shfl_up_sync(0xFFFFFFFFu, v, o);
        if (lane >= o) v += u;
    }
    if (lane == 31) s_w[w] = v;
    __syncthreads();
    if (t < 8) {
        int x = s_w[t];
        #pragma unroll
        for (int o = 1; o < 8; o <<= 1) {
            int u = __shfl_up_sync(0xFFu, x, o);
            if (t >= o) x += u;
        }
        s_w[t] = x;
    }
    __syncthreads();
    int warpoff = (w > 0) ? s_w[w - 1] : 0;
    int excl = warpoff + v - local;
    #pragma unroll
    for (int i = 0; i < 4; i++) {
        if (base + i < NN) g_rowstart[base + i] = excl;
        excl += d[i];
    }
    if (t == 0) g_bsum[b] = s_w[7];
}

__global__ void k_scan2() {
    __shared__ int sb[128];
    int t = threadIdx.x;
    int NB = (NN + 1023) / 1024;
    sb[t] = (t < NB) ? g_bsum[t] : 0;
    __syncthreads();
    for (int o = 1; o < 128; o <<= 1) {
        int u = (t >= o) ? sb[t - o] : 0;
        __syncthreads();
        sb[t] += u;
        __syncthreads();
    }
    g_boff[t] = (t > 0) ? sb[t - 1] : 0;
}

__global__ void k_scan3() {
    int i = blockIdx.x * blockDim.x + threadIdx.x;
    if (i < NN) {
        int v = g_rowstart[i] + g_boff[i >> 10];
        g_rowstart[i] = v;
        g_cursor[i] = v;
    }
    if (i == 0) g_rowstart[NN] = EE;
}

__global__ void k_fill() {
    int e = blockIdx.x * blockDim.x + threadIdx.x;
    if (e >= EE) return;
    int d = g_dst[e];
    int slot = atomicAdd(&g_cursor[d], 1);
    g_ssrc[slot] = g_src[e];
}

// ---------------- HMMA GEMM: one 128x128 tile per block ----------------------
// smem: sA [128][ASTRIDE] bf16 | sB [128][ASTRIDE] bf16 | reductions/vectors
#define SA_BYTES (HH * ASTRIDE * 2)
#define SB_OFF   SA_BYTES
#define SAS_OFF  (2 * SA_BYTES)
#define SAD_OFF  (SAS_OFF + 512)
#define SAVS_OFF (SAD_OFF + 512)
#define SAVD_OFF (SAVS_OFF + 512)
#define SSH_OFF  (SAVD_OFF + 512)
#define SSC_OFF  (SSH_OFF + 512)
#define SGB_OFF  (SSC_OFF + 512)
#define GEMM_SMEM (SGB_OFF + 512)

__global__ void __launch_bounds__(256, 1)
k_gemm_mma(const float* __restrict__ X, int layer, float* __restrict__ Y,
           const float* __restrict__ avs, const float* __restrict__ avd,
           int donorm) {
    extern __shared__ char smem[];
    uint32_t sbase = smem_u32(smem);
    int tid = threadIdx.x;
    int wid = tid >> 5, lane = tid & 31;
    int row0 = blockIdx.x << 7;
    int nrows = NN - row0; if (nrows > 128) nrows = 128;

    float* sAS = (float*)(smem + SAS_OFF);
    float* sAD = (float*)(smem + SAD_OFF);
    float* sAVS = (float*)(smem + SAVS_OFF);
    float* sAVD = (float*)(smem + SAVD_OFF);

    if (tid < 128) {
        sAVS[tid] = avs[tid];
        sAVD[tid] = avd[tid];
        sAS[tid] = 0.f; sAD[tid] = 0.f;
        if (donorm) {
            ((float*)(smem + SSH_OFF))[tid] = g_shift[tid];
            ((float*)(smem + SSC_OFF))[tid] = g_scale[tid];
            ((float*)(smem + SGB_OFF))[tid] = g_gb[tid];
        }
    }
    // copy W image (67584 B = 4224 float4)
    {
        const float4* src = (const float4*)(g_Wimg + (long long)layer * IMG_ELEMS);
        float4* dst = (float4*)(smem + SB_OFF);
        for (int i = tid; i < 4224; i += 256) dst[i] = src[i];
    }
    __syncthreads();   // sSH/sSC/sGB visible for staging below

    // ---- stage X tile: load fp32, optional norm, split to [Xh|Xl] ----
    #pragma unroll 4
    for (int i = 0; i < 16; i++) {
        int c = i * 256 + tid;          // float4 chunk (4096 total)
        int r = c >> 5, k4 = c & 31;
        float4 v = make_float4(0.f, 0.f, 0.f, 0.f);
        if (r < nrows) {
            v = ((const float4*)(X + (long long)(row0 + r) * HH))[k4];
            if (donorm) {
                float4 sh = ((const float4*)(smem + SSH_OFF))[k4];
                float4 sc = ((const float4*)(smem + SSC_OFF))[k4];
                float4 bb = ((const float4*)(smem + SGB_OFF))[k4];
                v.x = lrelu((v.x - sh.x) * sc.x + bb.x, 0.01f);
                v.y = lrelu((v.y - sh.y) * sc.y + bb.y, 0.01f);
                v.z = lrelu((v.z - sh.z) * sc.z + bb.z, 0.01f);
                v.w = lrelu((v.w - sh.w) * sc.w + bb.w, 0.01f);
            }
        }
        __nv_bfloat16 h0 = __float2bfloat16_rn(v.x), h1 = __float2bfloat16_rn(v.y);
        __nv_bfloat16 h2 = __float2bfloat16_rn(v.z), h3 = __float2bfloat16_rn(v.w);
        __nv_bfloat162 hp0; hp0.x = h0; hp0.y = h1;
        __nv_bfloat162 hp1; hp1.x = h2; hp1.y = h3;
        __nv_bfloat162 lp0 = __floats2bfloat162_rn(v.x - __bfloat162float(h0),
                                                   v.y - __bfloat162float(h1));
        __nv_bfloat162 lp1 = __floats2bfloat162_rn(v.z - __bfloat162float(h2),
                                                   v.w - __bfloat162float(h3));
        int k0 = k4 << 2;
        char* A = smem;
        uint2 hv = make_uint2(*(unsigned*)&hp0, *(unsigned*)&hp1);
        uint2 lv = make_uint2(*(unsigned*)&lp0, *(unsigned*)&lp1);
        *(uint2*)(A + (r * ASTRIDE + k0) * 2) = hv;
        *(uint2*)(A + (r * ASTRIDE + 128 + k0) * 2) = lv;
    }
    __syncthreads();

    // ---- mma mainloop ----
    // warp (m,n) layout: m0 = (wid>>1)*32, n0 = (wid&1)*64
    int m0 = (wid >> 1) << 5;
    int n0 = (wid & 1) << 6;
    float acc[2][8][4];
    #pragma unroll
    for (int mb = 0; mb < 2; mb++)
        #pragma unroll
        for (int nb = 0; nb < 8; nb++)
            #pragma unroll
            for (int j = 0; j < 4; j++) acc[mb][nb][j] = 0.f;

    int arow = m0 + (lane & 7) + ((lane >> 3) & 1) * 8;
    uint32_t aAddr = sbase + (arow * ASTRIDE + ((lane >> 4) & 1) * 8) * 2;
    int brow = n0 + (lane & 7) + ((lane >> 4) & 1) * 8;
    uint32_t bAddr = sbase + SB_OFF + (brow * ASTRIDE + ((lane >> 3) & 1) * 8) * 2;

    #pragma unroll
    for (int kk = 0; kk < 24; kk++) {
        int term = kk >> 3, ks = kk & 7;
        int a_off = ks * 16 + ((term == 1) ? 128 : 0);
        int b_off = ks * 16 + ((term == 2) ? 128 : 0);
        uint32_t af[2][4];
        ldm_x4(af[0], aAddr + a_off * 2);
        ldm_x4(af[1], aAddr + a_off * 2 + 16 * ASTRIDE * 2);
        uint32_t bf[4][4];
        #pragma unroll
        for (int nbp = 0; nbp < 4; nbp++)
            ldm_x4(bf[nbp], bAddr + b_off * 2 + nbp * 16 * ASTRIDE * 2);
        #pragma unroll
        for (int mb = 0; mb < 2; mb++)
            #pragma unroll
            for (int nbp = 0; nbp < 4; nbp++) {
                mma16816(acc[mb][2 * nbp],     af[mb], &bf[nbp][0]);
                mma16816(acc[mb][2 * nbp + 1], af[mb], &bf[nbp][2]);
            }
    }

    // ---- epilogue: store Y + attention dots ----
    int qrow = lane >> 2;          // 0..7
    int qcol = (lane & 3) << 1;    // 0,2,4,6
    #pragma unroll
    for (int mb = 0; mb < 2; mb++) {
        int rlo = m0 + mb * 16 + qrow;
        int rhi = rlo + 8;
        float as_lo = 0.f, ad_lo = 0.f, as_hi = 0.f, ad_hi = 0.f;
        #pragma unroll
        for (int nb = 0; nb < 8; nb++) {
            int col = n0 + nb * 8 + qcol;
            float c0 = acc[mb][nb][0], c1 = acc[mb][nb][1];
            float c2 = acc[mb][nb][2], c3 = acc[mb][nb][3];
            float s0 = sAVS[col], s1 = sAVS[col + 1];
            float d0 = sAVD[col], d1 = sAVD[col + 1];
            as_lo += c0 * s0 + c1 * s1;  ad_lo += c0 * d0 + c1 * d1;
            as_hi += c2 * s0 + c3 * s1;  ad_hi += c2 * d0 + c3 * d1;
            if (row0 + rlo < NN) {
                float2* p = (float2*)(Y + (long long)(row0 + rlo) * HH + col);
                *p = make_float2(c0, c1);
            }
            if (row0 + rhi < NN) {
                float2* p = (float2*)(Y + (long long)(row0 + rhi) * HH + col);
                *p = make_float2(c2, c3);
            }
        }
        // quad reduce (lanes sharing qrow)
        #pragma unroll
        for (int o = 1; o < 4; o <<= 1) {
            as_lo += __shfl_xor_sync(0xFFFFFFFFu, as_lo, o);
            ad_lo += __shfl_xor_sync(0xFFFFFFFFu, ad_lo, o);
            as_hi += __shfl_xor_sync(0xFFFFFFFFu, as_hi, o);
            ad_hi += __shfl_xor_sync(0xFFFFFFFFu, ad_hi, o);
        }
        if ((lane & 3) == 0) {
            atomicAdd(&sAS[rlo], as_lo); atomicAdd(&sAD[rlo], ad_lo);
            atomicAdd(&sAS[rhi], as_hi); atomicAdd(&sAD[rhi], ad_hi);
        }
    }
    __syncthreads();
    if (tid < 128) {
        int r = row0 + tid;
        if (r < NN) { g_as[r] = sAS[tid]; g_ad[r] = sAD[tid]; }
    }
}

// ---------------- GAT aggregation: per-dst-node warp, CSR --------------------
__global__ void k_gat_agg(const float* __restrict__ hW, float* __restrict__ hout,
                          const float* __restrict__ bias) {
    int node = (blockIdx.x * blockDim.x + threadIdx.x) >> 5;
    int lane = threadIdx.x & 31;
    if (node >= NN) return;
    int rs = g_rowstart[node], re = g_rowstart[node + 1];
    float ad_d = g_ad[node];
    float m = -1e30f, s = 0.f;
    for (int i = rs + lane; i < re; i += 32) {
        int src = g_ssrc[i];
        float x = lrelu(g_as[src] + ad_d, 0.2f);
        if (x > m) { s = s * __expf(m - x) + 1.f; m = x; }
        else       { s += __expf(x - m); }
    }
    #pragma unroll
    for (int o = 16; o; o >>= 1) {
        float om = __shfl_xor_sync(0xFFFFFFFFu, m, o);
        float os = __shfl_xor_sync(0xFFFFFFFFu, s, o);
        float nm = fmaxf(m, om);
        s = s * __expf(m - nm) + os * __expf(om - nm);
        m = nm;
    }
    float4 bb = ((const float4*)bias)[lane];
    float4 acc = bb;
    if (re > rs) {
        float inv = 1.f / (s + 1e-16f);
        for (int i = rs; i < re; ++i) {
            int src = g_ssrc[i];
            float alpha = __expf(lrelu(g_as[src] + ad_d, 0.2f) - m) * inv;
            float4 v = ((const float4*)(hW + (long long)src * HH))[lane];
            acc.x += alpha * v.x; acc.y += alpha * v.y;
            acc.z += alpha * v.z; acc.w += alpha * v.w;
        }
    }
    ((float4*)(hout + (long long)node * HH))[lane] = acc;
}

// ---------------- GraphNorm -------------------------------------------------
__global__ void k_zero_stats() {
    int c = threadIdx.x;
    if (c < HH) { g_colsum[c] = 0.f; g_colsq[c] = 0.f; }
}

__global__ void k_colstats(const float* __restrict__ h) {
    int c = threadIdx.x;
    float sum = 0.f, sq = 0.f;
    for (int r = blockIdx.x; r < NN; r += gridDim.x) {
        float v = h[(long long)r * HH + c];
        sum += v; sq += v * v;
    }
    atomicAdd(&g_colsum[c], sum);
    atomicAdd(&g_colsq[c], sq);
}

__global__ void k_norm_prep(const float* __restrict__ w, const float* __restrict__ b,
                            const float* __restrict__ ms) {
    int c = threadIdx.x;
    if (c >= HH) return;
    float invN = 1.0f / (float)NN;
    float mean = g_colsum[c] * invN;
    float ex2 = g_colsq[c] * invN;
    float s = ms[c];
    float var = ex2 - 2.f * s * mean * mean + s * s * mean * mean;
    g_shift[c] = mean * s;
    g_scale[c] = w[c] * rsqrtf(var + EPSN);
    g_gb[c] = b[c];
}

// ---------------- pooling + MLP ---------------------------------------------
#define PCH 256
__global__ void k_pool2(const float* __restrict__ h) {
    int c = threadIdx.x;
    int r0 = blockIdx.x * PCH;
    int rend = r0 + PCH; if (rend > NN) rend = NN;
    if (r0 >= NN) return;
    int cur = g_batch[r0];
    float acc = 0.f;
    for (int r = r0; r < rend; r++) {
        int b = g_batch[r];
        if (b != cur) { atomicAdd(&g_pool[cur * HH + c], acc); acc = 0.f; cur = b; }
        acc += h[(long long)r * HH + c];
    }
    atomicAdd(&g_pool[cur * HH + c], acc);
}

__global__ void k_mlp1(const float* __restrict__ W1, const float* __restrict__ b1) {
    __shared__ float sp[HH];
    int g = blockIdx.x, c = threadIdx.x;
    sp[c] = g_pool[g * HH + c];
    __syncthreads();
    float acc = b1[c];
    #pragma unroll 4
    for (int k = 0; k < HH; k++) acc += sp[k] * W1[k * HH + c];
    g_z[g * HH + c] = lrelu(acc, 0.01f);
}

__global__ void k_mlp2(const float* __restrict__ W2, const float* __restrict__ b2,
                       float* __restrict__ out) {
    __shared__ float sz[HH];
    int g = blockIdx.x, a = threadIdx.x;
    sz[a] = g_z[g * HH + a];
    sz[a + 64] = g_z[g * HH + a + 64];
    __syncthreads();
    float acc = b2[a];
    #pragma unroll 4
    for (int k = 0; k < HH; k++) acc += sz[k] * W2[k * AA + a];
    out[g * AA + a] = acc;
}

// ---------------- launcher ---------------------------------------------------
extern "C" void kernel_launch(void* const* d_in, const int* in_sizes, int n_in,
                              void* d_out, int out_size) {
    const float* x        = (const float*)d_in[0];
    const void*  e_raw    = d_in[1];
    const void*  b_raw    = d_in[2];
    const float* Ws       = (const float*)d_in[3];
    const float* att_src  = (const float*)d_in[4];
    const float* att_dst  = (const float*)d_in[5];
    const float* conv_bias= (const float*)d_in[6];
    const float* gn_w     = (const float*)d_in[7];
    const float* gn_b     = (const float*)d_in[8];
    const float* gn_ms    = (const float*)d_in[9];
    const float* W1       = (const float*)d_in[10];
    const float* b1       = (const float*)d_in[11];
    const float* W2       = (const float*)d_in[12];
    const float* b2       = (const float*)d_in[13];

    float* bufA; float* bufB;
    cudaGetSymbolAddress((void**)&bufA, g_bufA);
    cudaGetSymbolAddress((void**)&bufB, g_bufB);

    cudaFuncSetAttribute(k_gemm_mma, cudaFuncAttributeMaxDynamicSharedMemorySize, GEMM_SMEM);

    const int eg = (EE + 255) / 256;
    const int ng = (NN + 255) / 256;
    const int NB = (NN + 1023) / 1024;

    k_detect<<<1, 256>>>(e_raw, b_raw);
    k_cvt<<<eg, 256>>>(e_raw, b_raw);
    k_prepW<<<(LL * HH * HH + 255) / 256, 256>>>(Ws);
    k_hist<<<eg, 256>>>();
    k_scan1<<<NB, 256>>>();
    k_scan2<<<1, 128>>>();
    k_scan3<<<ng, 256>>>();
    k_fill<<<eg, 256>>>();

    const int agg_grid = (NN * 32 + 255) / 256;

    for (int l = 0; l < LL; l++) {
        const float* hin = (l == 0) ? x : bufB;
        k_gemm_mma<<<NTILES, 256, GEMM_SMEM>>>(hin, l, bufA,
                                               att_src + l * HH, att_dst + l * HH,
                                               l > 0 ? 1 : 0);
        k_gat_agg<<<agg_grid, 256>>>(bufA, bufB, conv_bias + l * HH);
        if (l < LL - 1) {
            k_zero_stats<<<1, 128>>>();
            k_colstats<<<512, 128>>>(bufB);
            k_norm_prep<<<1, 128>>>(gn_w + l * HH, gn_b + l * HH, gn_ms + l * HH);
        }
    }

    k_pool2<<<(NN + PCH - 1) / PCH, 128>>>(bufB);
    k_mlp1<<<GG, 128>>>(W1, b1);
    k_mlp2<<<GG, 64>>>(W2, b2, (float*)d_out);
}

// round 5
// speedup vs baseline: 1.6691x; 1.2001x over previous
#include <cuda_runtime.h>
#include <cuda_bf16.h>
#include <cstdint>

#define NN 100000
#define EE 600000
#define HH 128
#define AA 64
#define GG 64
#define LL 3
#define EPSN 1e-5f
#define NTILES 782          // ceil(100000/128)
#define ASTRIDE 264         // padded bf16 cols (K=256 + 8 pad) -> conflict-free ldmatrix
#define IMG_ELEMS (HH * ASTRIDE)

// ---------------- scratch (device globals) ----------------------------------
__device__ float g_bufA[NN * HH];
__device__ float g_bufB[NN * HH];
__device__ float g_as[NN], g_ad[NN];
__device__ int g_src[EE], g_dst[EE];
__device__ int g_batch[NN];
__device__ int g_deg[NN];
__device__ int g_rowstart[NN + 1];
__device__ int g_cursor[NN];
__device__ int g_ssrc[EE];
__device__ int g_bsum[128], g_boff[128];
__device__ float g_colsum[HH], g_colsq[HH];
__device__ float g_shift[HH], g_scale[HH], g_gb[HH];
__device__ float g_pool[GG * HH];
__device__ float g_z[GG * HH];
__device__ int g_edge_is32, g_batch_is32;
__device__ __align__(16) __nv_bfloat16 g_Wimg[LL * IMG_ELEMS];  // Wt[n][k]: [Wh | Wl], padded

__device__ __forceinline__ float lrelu(float x, float a) { return x > 0.f ? x : a * x; }

__device__ __forceinline__ uint32_t smem_u32(const void* p) {
    uint32_t a;
    asm("{ .reg .u64 t; cvta.to.shared.u64 t, %1; cvt.u32.u64 %0, t; }" : "=r"(a) : "l"(p));
    return a;
}
__device__ __forceinline__ void ldm_x4(uint32_t* r, uint32_t addr) {
    asm volatile("ldmatrix.sync.aligned.m8n8.x4.shared.b16 {%0,%1,%2,%3}, [%4];"
                 : "=r"(r[0]), "=r"(r[1]), "=r"(r[2]), "=r"(r[3]) : "r"(addr));
}
__device__ __forceinline__ void mma16816(float* c, const uint32_t* a, const uint32_t* b) {
    asm volatile("mma.sync.aligned.m16n8k16.row.col.f32.bf16.bf16.f32 "
                 "{%0,%1,%2,%3}, {%4,%5,%6,%7}, {%8,%9}, {%0,%1,%2,%3};"
                 : "+f"(c[0]), "+f"(c[1]), "+f"(c[2]), "+f"(c[3])
                 : "r"(a[0]), "r"(a[1]), "r"(a[2]), "r"(a[3]), "r"(b[0]), "r"(b[1]));
}
__device__ __forceinline__ void cpa16(uint32_t dst, const void* src, int sz) {
    asm volatile("cp.async.cg.shared.global [%0], [%1], 16, %2;"
                 :: "r"(dst), "l"(src), "r"(sz) : "memory");
}
#define CPA_COMMIT() asm volatile("cp.async.commit_group;" ::: "memory")
#define CPA_WAIT0()  asm volatile("cp.async.wait_group 0;" ::: "memory")

// ---------------- dtype detection ------------------------------------------
__global__ void k_detect(const void* eraw, const void* braw) {
    __shared__ int s_e, s_b;
    if (threadIdx.x == 0) { s_e = 0; s_b = 0; }
    __syncthreads();
    const long long* e64 = (const long long*)eraw;
    const long long* b64 = (const long long*)braw;
    int bad_e = 0, bad_b = 0;
    for (int i = threadIdx.x; i < 1024; i += blockDim.x) {
        long long v = e64[(long long)i * (EE / 1024)];
        if (v < 0 || v >= NN) bad_e = 1;
        long long bv = b64[(long long)i * ((NN / 2) / 1024)];
        if (bv < 0 || bv >= GG) bad_b = 1;
    }
    if (bad_e) atomicOr(&s_e, 1);
    if (bad_b) atomicOr(&s_b, 1);
    __syncthreads();
    if (threadIdx.x == 0) { g_edge_is32 = s_e; g_batch_is32 = s_b; }
}

__global__ void k_cvt(const void* eraw, const void* braw) {
    int i = blockIdx.x * blockDim.x + threadIdx.x;
    if (i < EE) {
        if (g_edge_is32) {
            const int* p = (const int*)eraw;
            g_src[i] = p[i]; g_dst[i] = p[EE + i];
        } else {
            const long long* p = (const long long*)eraw;
            g_src[i] = (int)p[i]; g_dst[i] = (int)p[EE + i];
        }
    }
    if (i < NN) {
        if (g_batch_is32) g_batch[i] = ((const int*)braw)[i];
        else              g_batch[i] = (int)((const long long*)braw)[i];
        g_deg[i] = 0;
    }
    if (i < GG * HH) g_pool[i] = 0.f;
}

// ---------------- W prep ----------------------------------------------------
__global__ void k_prepW(const float* __restrict__ Ws) {
    int i = blockIdx.x * blockDim.x + threadIdx.x;
    if (i >= LL * HH * HH) return;
    int l = i / (HH * HH);
    int r = i - l * HH * HH;
    int k = r >> 7;
    int n = r & 127;
    float w = Ws[i];
    __nv_bfloat16 hi = __float2bfloat16_rn(w);
    float resid = w - __bfloat162float(hi);
    __nv_bfloat16 lo = __float2bfloat16_rn(resid);
    __nv_bfloat16* img = g_Wimg + (long long)l * IMG_ELEMS;
    img[n * ASTRIDE + k] = hi;
    img[n * ASTRIDE + 128 + k] = lo;
}

// ---------------- CSR build -------------------------------------------------
__global__ void k_hist() {
    int e = blockIdx.x * blockDim.x + threadIdx.x;
    if (e < EE) atomicAdd(&g_deg[g_dst[e]], 1);
}

__global__ void k_scan1() {
    __shared__ int s_w[8];
    int b = blockIdx.x, t = threadIdx.x;
    int base = b * 1024 + t * 4;
    int d[4];
    #pragma unroll
    for (int i = 0; i < 4; i++) d[i] = (base + i < NN) ? g_deg[base + i] : 0;
    int local = d[0] + d[1] + d[2] + d[3];
    int lane = t & 31, w = t >> 5;
    int v = local;
    #pragma unroll
    for (int o = 1; o < 32; o <<= 1) {
        int u = __shfl_up_sync(0xFFFFFFFFu, v, o);
        if (lane >= o) v += u;
    }
    if (lane == 31) s_w[w] = v;
    __syncthreads();
    if (t < 8) {
        int x = s_w[t];
        #pragma unroll
        for (int o = 1; o < 8; o <<= 1) {
            int u = __shfl_up_sync(0xFFu, x, o);
            if (t >= o) x += u;
        }
        s_w[t] = x;
    }
    __syncthreads();
    int warpoff = (w > 0) ? s_w[w - 1] : 0;
    int excl = warpoff + v - local;
    #pragma unroll
    for (int i = 0; i < 4; i++) {
        if (base + i < NN) g_rowstart[base + i] = excl;
        excl += d[i];
    }
    if (t == 0) g_bsum[b] = s_w[7];
}

__global__ void k_scan2() {
    __shared__ int sb[128];
    int t = threadIdx.x;
    int NB = (NN + 1023) / 1024;
    sb[t] = (t < NB) ? g_bsum[t] : 0;
    __syncthreads();
    for (int o = 1; o < 128; o <<= 1) {
        int u = (t >= o) ? sb[t - o] : 0;
        __syncthreads();
        sb[t] += u;
        __syncthreads();
    }
    g_boff[t] = (t > 0) ? sb[t - 1] : 0;
}

__global__ void k_scan3() {
    int i = blockIdx.x * blockDim.x + threadIdx.x;
    if (i < NN) {
        int v = g_rowstart[i] + g_boff[i >> 10];
        g_rowstart[i] = v;
        g_cursor[i] = v;
    }
    if (i == 0) g_rowstart[NN] = EE;
}

__global__ void k_fill() {
    int e = blockIdx.x * blockDim.x + threadIdx.x;
    if (e >= EE) return;
    int d = g_dst[e];
    int slot = atomicAdd(&g_cursor[d], 1);
    g_ssrc[slot] = g_src[e];
}

// ---------------- HMMA GEMM: persistent, cp.async pipelined ------------------
// smem: sA bf16 [128][ASTRIDE] | sB bf16 [128][ASTRIDE] | stage fp32 [128][128] | vecs
#define SA_BYTES  (HH * ASTRIDE * 2)          // 67584
#define SB_OFF    SA_BYTES
#define STAGE_OFF (2 * SA_BYTES)              // 135168
#define VEC_OFF   (STAGE_OFF + 65536)         // 200704
#define SAS_OFF   (VEC_OFF)
#define SAD_OFF   (VEC_OFF + 512)
#define SAVS_OFF  (VEC_OFF + 1024)
#define SAVD_OFF  (VEC_OFF + 1536)
#define SSH_OFF   (VEC_OFF + 2048)
#define SSC_OFF   (VEC_OFF + 2560)
#define SGB_OFF   (VEC_OFF + 3072)
#define GEMM_SMEM (VEC_OFF + 3584)            // 204288

__device__ __forceinline__ void gemm_prefetch(const float* __restrict__ X, int row0,
                                              uint32_t stage, int tid) {
    int nrows = NN - row0; if (nrows > 128) nrows = 128;
    #pragma unroll
    for (int i = 0; i < 16; i++) {
        int c = i * 256 + tid;
        int r = c >> 5, k4 = c & 31;
        int rr = r < nrows ? r : 0;
        const float4* src = ((const float4*)(X + (long long)(row0 + rr) * HH)) + k4;
        cpa16(stage + c * 16, src, r < nrows ? 16 : 0);
    }
    CPA_COMMIT();
}

__global__ void __launch_bounds__(256, 1)
k_gemm_mma(const float* __restrict__ X, int layer, float* __restrict__ Y,
           const float* __restrict__ avs, const float* __restrict__ avd,
           int donorm) {
    extern __shared__ char smem[];
    uint32_t sbase = smem_u32(smem);
    int tid = threadIdx.x;
    int wid = tid >> 5, lane = tid & 31;

    float* sAS = (float*)(smem + SAS_OFF);
    float* sAD = (float*)(smem + SAD_OFF);
    float* sAVS = (float*)(smem + SAVS_OFF);
    float* sAVD = (float*)(smem + SAVD_OFF);

    if (tid < 128) {
        sAVS[tid] = avs[tid];
        sAVD[tid] = avd[tid];
        if (donorm) {
            ((float*)(smem + SSH_OFF))[tid] = g_shift[tid];
            ((float*)(smem + SSC_OFF))[tid] = g_scale[tid];
            ((float*)(smem + SGB_OFF))[tid] = g_gb[tid];
        }
    }
    // copy W image once per block (67584 B = 4224 float4)
    {
        const float4* src = (const float4*)(g_Wimg + (long long)layer * IMG_ELEMS);
        float4* dst = (float4*)(smem + SB_OFF);
        for (int i = tid; i < 4224; i += 256) dst[i] = src[i];
    }

    // mma addressing (fixed per thread)
    int m0 = (wid >> 1) << 5;
    int n0 = (wid & 1) << 6;
    int arow = m0 + (lane & 7) + ((lane >> 3) & 1) * 8;
    uint32_t aAddr = sbase + (arow * ASTRIDE + ((lane >> 4) & 1) * 8) * 2;
    int brow = n0 + (lane & 7) + ((lane >> 4) & 1) * 8;
    uint32_t bAddr = sbase + SB_OFF + (brow * ASTRIDE + ((lane >> 3) & 1) * 8) * 2;
    int qrow = lane >> 2;
    int qcol = (lane & 3) << 1;

    // prefetch first tile
    int t0 = blockIdx.x;
    if (t0 < NTILES) gemm_prefetch(X, t0 << 7, sbase + STAGE_OFF, tid);

    for (int t = t0; t < NTILES; t += gridDim.x) {
        int row0 = t << 7;
        int nrows = NN - row0; if (nrows > 128) nrows = 128;
        CPA_WAIT0();
        __syncthreads();   // stage ready; prev epilogue's sAS reads done

        // ---- convert stage -> sA (bf16 split, optional norm); zero sAS/sAD ----
        if (tid < 128) { sAS[tid] = 0.f; sAD[tid] = 0.f; }
        #pragma unroll 4
        for (int i = 0; i < 16; i++) {
            int c = i * 256 + tid;
            int r = c >> 5, k4 = c & 31;
            float4 v = ((const float4*)(smem + STAGE_OFF))[c];
            if (donorm && r < nrows) {
                float4 sh = ((const float4*)(smem + SSH_OFF))[k4];
                float4 sc = ((const float4*)(smem + SSC_OFF))[k4];
                float4 bb = ((const float4*)(smem + SGB_OFF))[k4];
                v.x = lrelu((v.x - sh.x) * sc.x + bb.x, 0.01f);
                v.y = lrelu((v.y - sh.y) * sc.y + bb.y, 0.01f);
                v.z = lrelu((v.z - sh.z) * sc.z + bb.z, 0.01f);
                v.w = lrelu((v.w - sh.w) * sc.w + bb.w, 0.01f);
            }
            __nv_bfloat16 h0 = __float2bfloat16_rn(v.x), h1 = __float2bfloat16_rn(v.y);
            __nv_bfloat16 h2 = __float2bfloat16_rn(v.z), h3 = __float2bfloat16_rn(v.w);
            __nv_bfloat162 hp0; hp0.x = h0; hp0.y = h1;
            __nv_bfloat162 hp1; hp1.x = h2; hp1.y = h3;
            __nv_bfloat162 lp0 = __floats2bfloat162_rn(v.x - __bfloat162float(h0),
                                                       v.y - __bfloat162float(h1));
            __nv_bfloat162 lp1 = __floats2bfloat162_rn(v.z - __bfloat162float(h2),
                                                       v.w - __bfloat162float(h3));
            int k0 = k4 << 2;
            uint2 hv = make_uint2(*(unsigned*)&hp0, *(unsigned*)&hp1);
            uint2 lv = make_uint2(*(unsigned*)&lp0, *(unsigned*)&lp1);
            *(uint2*)(smem + (r * ASTRIDE + k0) * 2) = hv;
            *(uint2*)(smem + (r * ASTRIDE + 128 + k0) * 2) = lv;
        }
        __syncthreads();   // sA ready, stage consumed

        // ---- prefetch next tile while mma runs ----
        int tn = t + gridDim.x;
        if (tn < NTILES) gemm_prefetch(X, tn << 7, sbase + STAGE_OFF, tid);

        // ---- mma mainloop ----
        float acc[2][8][4];
        #pragma unroll
        for (int mb = 0; mb < 2; mb++)
            #pragma unroll
            for (int nb = 0; nb < 8; nb++)
                #pragma unroll
                for (int j = 0; j < 4; j++) acc[mb][nb][j] = 0.f;

        #pragma unroll
        for (int kk = 0; kk < 24; kk++) {
            int term = kk >> 3, ks = kk & 7;
            int a_off = ks * 16 + ((term == 1) ? 128 : 0);
            int b_off = ks * 16 + ((term == 2) ? 128 : 0);
            uint32_t af[2][4];
            ldm_x4(af[0], aAddr + a_off * 2);
            ldm_x4(af[1], aAddr + a_off * 2 + 16 * ASTRIDE * 2);
            uint32_t bf[4][4];
            #pragma unroll
            for (int nbp = 0; nbp < 4; nbp++)
                ldm_x4(bf[nbp], bAddr + b_off * 2 + nbp * 16 * ASTRIDE * 2);
            #pragma unroll
            for (int mb = 0; mb < 2; mb++)
                #pragma unroll
                for (int nbp = 0; nbp < 4; nbp++) {
                    mma16816(acc[mb][2 * nbp],     af[mb], &bf[nbp][0]);
                    mma16816(acc[mb][2 * nbp + 1], af[mb], &bf[nbp][2]);
                }
        }

        // ---- epilogue: store Y + attention dots ----
        #pragma unroll
        for (int mb = 0; mb < 2; mb++) {
            int rlo = m0 + mb * 16 + qrow;
            int rhi = rlo + 8;
            float as_lo = 0.f, ad_lo = 0.f, as_hi = 0.f, ad_hi = 0.f;
            #pragma unroll
            for (int nb = 0; nb < 8; nb++) {
                int col = n0 + nb * 8 + qcol;
                float c0 = acc[mb][nb][0], c1 = acc[mb][nb][1];
                float c2 = acc[mb][nb][2], c3 = acc[mb][nb][3];
                float s0 = sAVS[col], s1 = sAVS[col + 1];
                float d0 = sAVD[col], d1 = sAVD[col + 1];
                as_lo += c0 * s0 + c1 * s1;  ad_lo += c0 * d0 + c1 * d1;
                as_hi += c2 * s0 + c3 * s1;  ad_hi += c2 * d0 + c3 * d1;
                if (rlo < nrows) {
                    float2* p = (float2*)(Y + (long long)(row0 + rlo) * HH + col);
                    *p = make_float2(c0, c1);
                }
                if (rhi < nrows) {
                    float2* p = (float2*)(Y + (long long)(row0 + rhi) * HH + col);
                    *p = make_float2(c2, c3);
                }
            }
            #pragma unroll
            for (int o = 1; o < 4; o <<= 1) {
                as_lo += __shfl_xor_sync(0xFFFFFFFFu, as_lo, o);
                ad_lo += __shfl_xor_sync(0xFFFFFFFFu, ad_lo, o);
                as_hi += __shfl_xor_sync(0xFFFFFFFFu, as_hi, o);
                ad_hi += __shfl_xor_sync(0xFFFFFFFFu, ad_hi, o);
            }
            if ((lane & 3) == 0) {
                atomicAdd(&sAS[rlo], as_lo); atomicAdd(&sAD[rlo], ad_lo);
                atomicAdd(&sAS[rhi], as_hi); atomicAdd(&sAD[rhi], ad_hi);
            }
        }
        __syncthreads();
        if (tid < nrows) {
            int r = row0 + tid;
            g_as[r] = sAS[tid]; g_ad[r] = sAD[tid];
        }
    }
}

// ---------------- GAT aggregation: per-dst-node warp, CSR --------------------
__global__ void k_gat_agg(const float* __restrict__ hW, float* __restrict__ hout,
                          const float* __restrict__ bias) {
    int node = (blockIdx.x * blockDim.x + threadIdx.x) >> 5;
    int lane = threadIdx.x & 31;
    if (node >= NN) return;
    int rs = g_rowstart[node], re = g_rowstart[node + 1];
    int deg = re - rs;
    float ad_d = g_ad[node];
    float4 acc = ((const float4*)bias)[lane];

    if (deg <= 32) {
        // fast path: lane-resident src + alpha, shfl broadcast
        int my_src = 0;
        float my_logit = -1e30f;
        if (lane < deg) {
            my_src = g_ssrc[rs + lane];
            my_logit = lrelu(g_as[my_src] + ad_d, 0.2f);
        }
        float m = my_logit;
        #pragma unroll
        for (int o = 16; o; o >>= 1) m = fmaxf(m, __shfl_xor_sync(0xFFFFFFFFu, m, o));
        float ex = (lane < deg) ? __expf(my_logit - m) : 0.f;
        float s = ex;
        #pragma unroll
        for (int o = 16; o; o >>= 1) s += __shfl_xor_sync(0xFFFFFFFFu, s, o);
        float my_alpha = ex / (s + 1e-16f);
        for (int j = 0; j < deg; j++) {
            int src = __shfl_sync(0xFFFFFFFFu, my_src, j);
            float alpha = __shfl_sync(0xFFFFFFFFu, my_alpha, j);
            float4 v = ((const float4*)(hW + (long long)src * HH))[lane];
            acc.x += alpha * v.x; acc.y += alpha * v.y;
            acc.z += alpha * v.z; acc.w += alpha * v.w;
        }
    } else {
        // generic path: online softmax then recompute
        float m = -1e30f, s = 0.f;
        for (int i = rs + lane; i < re; i += 32) {
            int src = g_ssrc[i];
            float x = lrelu(g_as[src] + ad_d, 0.2f);
            if (x > m) { s = s * __expf(m - x) + 1.f; m = x; }
            else       { s += __expf(x - m); }
        }
        #pragma unroll
        for (int o = 16; o; o >>= 1) {
            float om = __shfl_xor_sync(0xFFFFFFFFu, m, o);
            float os = __shfl_xor_sync(0xFFFFFFFFu, s, o);
            float nm = fmaxf(m, om);
            s = s * __expf(m - nm) + os * __expf(om - nm);
            m = nm;
        }
        float inv = 1.f / (s + 1e-16f);
        for (int i = rs; i < re; ++i) {
            int src = g_ssrc[i];
            float alpha = __expf(lrelu(g_as[src] + ad_d, 0.2f) - m) * inv;
            float4 v = ((const float4*)(hW + (long long)src * HH))[lane];
            acc.x += alpha * v.x; acc.y += alpha * v.y;
            acc.z += alpha * v.z; acc.w += alpha * v.w;
        }
    }
    ((float4*)(hout + (long long)node * HH))[lane] = acc;
}

// ---------------- GraphNorm -------------------------------------------------
__global__ void k_zero_stats() {
    int c = threadIdx.x;
    if (c < HH) { g_colsum[c] = 0.f; g_colsq[c] = 0.f; }
}

__global__ void k_colstats(const float* __restrict__ h) {
    int c = threadIdx.x;
    float sum = 0.f, sq = 0.f;
    for (int r = blockIdx.x; r < NN; r += gridDim.x) {
        float v = h[(long long)r * HH + c];
        sum += v; sq += v * v;
    }
    atomicAdd(&g_colsum[c], sum);
    atomicAdd(&g_colsq[c], sq);
}

__global__ void k_norm_prep(const float* __restrict__ w, const float* __restrict__ b,
                            const float* __restrict__ ms) {
    int c = threadIdx.x;
    if (c >= HH) return;
    float invN = 1.0f / (float)NN;
    float mean = g_colsum[c] * invN;
    float ex2 = g_colsq[c] * invN;
    float s = ms[c];
    float var = ex2 - 2.f * s * mean * mean + s * s * mean * mean;
    g_shift[c] = mean * s;
    g_scale[c] = w[c] * rsqrtf(var + EPSN);
    g_gb[c] = b[c];
}

// ---------------- pooling + MLP ---------------------------------------------
#define PCH 256
__global__ void k_pool2(const float* __restrict__ h) {
    int c = threadIdx.x;
    int r0 = blockIdx.x * PCH;
    int rend = r0 + PCH; if (rend > NN) rend = NN;
    if (r0 >= NN) return;
    int cur = g_batch[r0];
    float acc = 0.f;
    for (int r = r0; r < rend; r++) {
        int b = g_batch[r];
        if (b != cur) { atomicAdd(&g_pool[cur * HH + c], acc); acc = 0.f; cur = b; }
        acc += h[(long long)r * HH + c];
    }
    atomicAdd(&g_pool[cur * HH + c], acc);
}

__global__ void k_mlp1(const float* __restrict__ W1, const float* __restrict__ b1) {
    __shared__ float sp[HH];
    int g = blockIdx.x, c = threadIdx.x;
    sp[c] = g_pool[g * HH + c];
    __syncthreads();
    float acc = b1[c];
    #pragma unroll 4
    for (int k = 0; k < HH; k++) acc += sp[k] * W1[k * HH + c];
    g_z[g * HH + c] = lrelu(acc, 0.01f);
}

__global__ void k_mlp2(const float* __restrict__ W2, const float* __restrict__ b2,
                       float* __restrict__ out) {
    __shared__ float sz[HH];
    int g = blockIdx.x, a = threadIdx.x;
    sz[a] = g_z[g * HH + a];
    sz[a + 64] = g_z[g * HH + a + 64];
    __syncthreads();
    float acc = b2[a];
    #pragma unroll 4
    for (int k = 0; k < HH; k++) acc += sz[k] * W2[k * AA + a];
    out[g * AA + a] = acc;
}

// ---------------- launcher ---------------------------------------------------
extern "C" void kernel_launch(void* const* d_in, const int* in_sizes, int n_in,
                              void* d_out, int out_size) {
    const float* x        = (const float*)d_in[0];
    const void*  e_raw    = d_in[1];
    const void*  b_raw    = d_in[2];
    const float* Ws       = (const float*)d_in[3];
    const float* att_src  = (const float*)d_in[4];
    const float* att_dst  = (const float*)d_in[5];
    const float* conv_bias= (const float*)d_in[6];
    const float* gn_w     = (const float*)d_in[7];
    const float* gn_b     = (const float*)d_in[8];
    const float* gn_ms    = (const float*)d_in[9];
    const float* W1       = (const float*)d_in[10];
    const float* b1       = (const float*)d_in[11];
    const float* W2       = (const float*)d_in[12];
    const float* b2       = (const float*)d_in[13];

    float* bufA; float* bufB;
    cudaGetSymbolAddress((void**)&bufA, g_bufA);
    cudaGetSymbolAddress((void**)&bufB, g_bufB);

    cudaFuncSetAttribute(k_gemm_mma, cudaFuncAttributeMaxDynamicSharedMemorySize, GEMM_SMEM);

    const int eg = (EE + 255) / 256;
    const int ng = (NN + 255) / 256;
    const int NB = (NN + 1023) / 1024;

    k_detect<<<1, 256>>>(e_raw, b_raw);
    k_cvt<<<eg, 256>>>(e_raw, b_raw);
    k_prepW<<<(LL * HH * HH + 255) / 256, 256>>>(Ws);
    k_hist<<<eg, 256>>>();
    k_scan1<<<NB, 256>>>();
    k_scan2<<<1, 128>>>();
    k_scan3<<<ng, 256>>>();
    k_fill<<<eg, 256>>>();

    const int agg_grid = (NN * 32 + 255) / 256;

    for (int l = 0; l < LL; l++) {
        const float* hin = (l == 0) ? x : bufB;
        k_gemm_mma<<<148, 256, GEMM_SMEM>>>(hin, l, bufA,
                                            att_src + l * HH, att_dst + l * HH,
                                            l > 0 ? 1 : 0);
        k_gat_agg<<<agg_grid, 256>>>(bufA, bufB, conv_bias + l * HH);
        if (l < LL - 1) {
            k_zero_stats<<<1, 128>>>();
            k_colstats<<<512, 128>>>(bufB);
            k_norm_prep<<<1, 128>>>(gn_w + l * HH, gn_b + l * HH, gn_ms + l * HH);
        }
    }

    k_pool2<<<(NN + PCH - 1) / PCH, 128>>>(bufB);
    k_mlp1<<<GG, 128>>>(W1, b1);
    k_mlp2<<<GG, 64>>>(W2, b2, (float*)d_out);
}

// round 6
// speedup vs baseline: 2.1132x; 1.2661x over previous
#include <cuda_runtime.h>
#include <cuda_bf16.h>
#include <cstdint>

#define NN 100000
#define EE 600000
#define HH 128
#define AA 64
#define GG 64
#define LL 3
#define EPSN 1e-5f
#define NTILES 782          // ceil(100000/128)
#define ASTRIDE 264         // padded bf16 cols (K=256 + 8 pad) -> conflict-free ldmatrix
#define IMG_ELEMS (HH * ASTRIDE)
#define NPW 4               // nodes per warp in aggregation

// ---------------- scratch (device globals) ----------------------------------
__device__ float g_bufA[NN * HH];
__device__ float g_bufB[NN * HH];
__device__ float g_as[NN], g_ad[NN];
__device__ int g_src[EE], g_dst[EE];
__device__ int g_batch[NN];
__device__ int g_deg[NN];
__device__ int g_rowstart[NN + 1];
__device__ int g_cursor[NN];
__device__ int g_ssrc[EE];
__device__ int g_bsum[128], g_boff[128];
__device__ float g_colsum[HH], g_colsq[HH];
__device__ float g_shift[HH], g_scale[HH], g_gb[HH];
__device__ float g_pool[GG * HH];
__device__ float g_z[GG * HH];
__device__ int g_edge_is32, g_batch_is32;
__device__ __align__(16) __nv_bfloat16 g_Wimg[LL * IMG_ELEMS];

__device__ __forceinline__ float lrelu(float x, float a) { return x > 0.f ? x : a * x; }

__device__ __forceinline__ uint32_t smem_u32(const void* p) {
    uint32_t a;
    asm("{ .reg .u64 t; cvta.to.shared.u64 t, %1; cvt.u32.u64 %0, t; }" : "=r"(a) : "l"(p));
    return a;
}
__device__ __forceinline__ void ldm_x4(uint32_t* r, uint32_t addr) {
    asm volatile("ldmatrix.sync.aligned.m8n8.x4.shared.b16 {%0,%1,%2,%3}, [%4];"
                 : "=r"(r[0]), "=r"(r[1]), "=r"(r[2]), "=r"(r[3]) : "r"(addr));
}
__device__ __forceinline__ void mma16816(float* c, const uint32_t* a, const uint32_t* b) {
    asm volatile("mma.sync.aligned.m16n8k16.row.col.f32.bf16.bf16.f32 "
                 "{%0,%1,%2,%3}, {%4,%5,%6,%7}, {%8,%9}, {%0,%1,%2,%3};"
                 : "+f"(c[0]), "+f"(c[1]), "+f"(c[2]), "+f"(c[3])
                 : "r"(a[0]), "r"(a[1]), "r"(a[2]), "r"(a[3]), "r"(b[0]), "r"(b[1]));
}
__device__ __forceinline__ void cpa16(uint32_t dst, const void* src, int sz) {
    asm volatile("cp.async.cg.shared.global [%0], [%1], 16, %2;"
                 :: "r"(dst), "l"(src), "r"(sz) : "memory");
}
#define CPA_COMMIT() asm volatile("cp.async.commit_group;" ::: "memory")
#define CPA_WAIT0()  asm volatile("cp.async.wait_group 0;" ::: "memory")

// ---------------- dtype detection ------------------------------------------
__global__ void k_detect(const void* eraw, const void* braw) {
    __shared__ int s_e, s_b;
    if (threadIdx.x == 0) { s_e = 0; s_b = 0; }
    __syncthreads();
    const long long* e64 = (const long long*)eraw;
    const long long* b64 = (const long long*)braw;
    int bad_e = 0, bad_b = 0;
    for (int i = threadIdx.x; i < 1024; i += blockDim.x) {
        long long v = e64[(long long)i * (EE / 1024)];
        if (v < 0 || v >= NN) bad_e = 1;
        long long bv = b64[(long long)i * ((NN / 2) / 1024)];
        if (bv < 0 || bv >= GG) bad_b = 1;
    }
    if (bad_e) atomicOr(&s_e, 1);
    if (bad_b) atomicOr(&s_b, 1);
    __syncthreads();
    if (threadIdx.x == 0) { g_edge_is32 = s_e; g_batch_is32 = s_b; }
}

__global__ void k_cvt(const void* eraw, const void* braw) {
    int i = blockIdx.x * blockDim.x + threadIdx.x;
    if (i < EE) {
        if (g_edge_is32) {
            const int* p = (const int*)eraw;
            g_src[i] = p[i]; g_dst[i] = p[EE + i];
        } else {
            const long long* p = (const long long*)eraw;
            g_src[i] = (int)p[i]; g_dst[i] = (int)p[EE + i];
        }
    }
    if (i < NN) {
        if (g_batch_is32) g_batch[i] = ((const int*)braw)[i];
        else              g_batch[i] = (int)((const long long*)braw)[i];
        g_deg[i] = 0;
    }
    if (i < GG * HH) g_pool[i] = 0.f;
}

// ---------------- W prep ----------------------------------------------------
__global__ void k_prepW(const float* __restrict__ Ws) {
    int i = blockIdx.x * blockDim.x + threadIdx.x;
    if (i >= LL * HH * HH) return;
    int l = i / (HH * HH);
    int r = i - l * HH * HH;
    int k = r >> 7;
    int n = r & 127;
    float w = Ws[i];
    __nv_bfloat16 hi = __float2bfloat16_rn(w);
    float resid = w - __bfloat162float(hi);
    __nv_bfloat16 lo = __float2bfloat16_rn(resid);
    __nv_bfloat16* img = g_Wimg + (long long)l * IMG_ELEMS;
    img[n * ASTRIDE + k] = hi;
    img[n * ASTRIDE + 128 + k] = lo;
}

// ---------------- CSR build -------------------------------------------------
__global__ void k_hist() {
    int e = blockIdx.x * blockDim.x + threadIdx.x;
    if (e < EE) atomicAdd(&g_deg[g_dst[e]], 1);
}

__global__ void k_scan1() {
    __shared__ int s_w[8];
    int b = blockIdx.x, t = threadIdx.x;
    int base = b * 1024 + t * 4;
    int d[4];
    #pragma unroll
    for (int i = 0; i < 4; i++) d[i] = (base + i < NN) ? g_deg[base + i] : 0;
    int local = d[0] + d[1] + d[2] + d[3];
    int lane = t & 31, w = t >> 5;
    int v = local;
    #pragma unroll
    for (int o = 1; o < 32; o <<= 1) {
        int u = __shfl_up_sync(0xFFFFFFFFu, v, o);
        if (lane >= o) v += u;
    }
    if (lane == 31) s_w[w] = v;
    __syncthreads();
    if (t < 8) {
        int x = s_w[t];
        #pragma unroll
        for (int o = 1; o < 8; o <<= 1) {
            int u = __shfl_up_sync(0xFFu, x, o);
            if (t >= o) x += u;
        }
        s_w[t] = x;
    }
    __syncthreads();
    int warpoff = (w > 0) ? s_w[w - 1] : 0;
    int excl = warpoff + v - local;
    #pragma unroll
    for (int i = 0; i < 4; i++) {
        if (base + i < NN) g_rowstart[base + i] = excl;
        excl += d[i];
    }
    if (t == 0) g_bsum[b] = s_w[7];
}

__global__ void k_scan2() {
    __shared__ int sb[128];
    int t = threadIdx.x;
    int NB = (NN + 1023) / 1024;
    sb[t] = (t < NB) ? g_bsum[t] : 0;
    __syncthreads();
    for (int o = 1; o < 128; o <<= 1) {
        int u = (t >= o) ? sb[t - o] : 0;
        __syncthreads();
        sb[t] += u;
        __syncthreads();
    }
    g_boff[t] = (t > 0) ? sb[t - 1] : 0;
}

__global__ void k_scan3() {
    int i = blockIdx.x * blockDim.x + threadIdx.x;
    if (i < NN) {
        int v = g_rowstart[i] + g_boff[i >> 10];
        g_rowstart[i] = v;
        g_cursor[i] = v;
    }
    if (i == 0) g_rowstart[NN] = EE;
}

__global__ void k_fill() {
    int e = blockIdx.x * blockDim.x + threadIdx.x;
    if (e >= EE) return;
    int d = g_dst[e];
    int slot = atomicAdd(&g_cursor[d], 1);
    g_ssrc[slot] = g_src[e];
}

// ---------------- HMMA GEMM: persistent, cp.async pipelined ------------------
#define SA_BYTES  (HH * ASTRIDE * 2)
#define SB_OFF    SA_BYTES
#define STAGE_OFF (2 * SA_BYTES)
#define VEC_OFF   (STAGE_OFF + 65536)
#define SAS_OFF   (VEC_OFF)
#define SAD_OFF   (VEC_OFF + 512)
#define SAVS_OFF  (VEC_OFF + 1024)
#define SAVD_OFF  (VEC_OFF + 1536)
#define SSH_OFF   (VEC_OFF + 2048)
#define SSC_OFF   (VEC_OFF + 2560)
#define SGB_OFF   (VEC_OFF + 3072)
#define GEMM_SMEM (VEC_OFF + 3584)

__device__ __forceinline__ void gemm_prefetch(const float* __restrict__ X, int row0,
                                              uint32_t stage, int tid) {
    int nrows = NN - row0; if (nrows > 128) nrows = 128;
    #pragma unroll
    for (int i = 0; i < 16; i++) {
        int c = i * 256 + tid;
        int r = c >> 5, k4 = c & 31;
        int rr = r < nrows ? r : 0;
        const float4* src = ((const float4*)(X + (long long)(row0 + rr) * HH)) + k4;
        cpa16(stage + c * 16, src, r < nrows ? 16 : 0);
    }
    CPA_COMMIT();
}

__global__ void __launch_bounds__(256, 1)
k_gemm_mma(const float* __restrict__ X, int layer, float* __restrict__ Y,
           const float* __restrict__ avs, const float* __restrict__ avd,
           int donorm) {
    extern __shared__ char smem[];
    uint32_t sbase = smem_u32(smem);
    int tid = threadIdx.x;
    int wid = tid >> 5, lane = tid & 31;

    float* sAS = (float*)(smem + SAS_OFF);
    float* sAD = (float*)(smem + SAD_OFF);
    float* sAVS = (float*)(smem + SAVS_OFF);
    float* sAVD = (float*)(smem + SAVD_OFF);

    if (tid < 128) {
        sAVS[tid] = avs[tid];
        sAVD[tid] = avd[tid];
        if (donorm) {
            ((float*)(smem + SSH_OFF))[tid] = g_shift[tid];
            ((float*)(smem + SSC_OFF))[tid] = g_scale[tid];
            ((float*)(smem + SGB_OFF))[tid] = g_gb[tid];
        }
    }
    {
        const float4* src = (const float4*)(g_Wimg + (long long)layer * IMG_ELEMS);
        float4* dst = (float4*)(smem + SB_OFF);
        for (int i = tid; i < 4224; i += 256) dst[i] = src[i];
    }

    int m0 = (wid >> 1) << 5;
    int n0 = (wid & 1) << 6;
    int arow = m0 + (lane & 7) + ((lane >> 3) & 1) * 8;
    uint32_t aAddr = sbase + (arow * ASTRIDE + ((lane >> 4) & 1) * 8) * 2;
    int brow = n0 + (lane & 7) + ((lane >> 4) & 1) * 8;
    uint32_t bAddr = sbase + SB_OFF + (brow * ASTRIDE + ((lane >> 3) & 1) * 8) * 2;
    int qrow = lane >> 2;
    int qcol = (lane & 3) << 1;

    int t0 = blockIdx.x;
    if (t0 < NTILES) gemm_prefetch(X, t0 << 7, sbase + STAGE_OFF, tid);

    for (int t = t0; t < NTILES; t += gridDim.x) {
        int row0 = t << 7;
        int nrows = NN - row0; if (nrows > 128) nrows = 128;
        CPA_WAIT0();
        __syncthreads();

        if (tid < 128) { sAS[tid] = 0.f; sAD[tid] = 0.f; }
        #pragma unroll 4
        for (int i = 0; i < 16; i++) {
            int c = i * 256 + tid;
            int r = c >> 5, k4 = c & 31;
            float4 v = ((const float4*)(smem + STAGE_OFF))[c];
            if (donorm && r < nrows) {
                float4 sh = ((const float4*)(smem + SSH_OFF))[k4];
                float4 sc = ((const float4*)(smem + SSC_OFF))[k4];
                float4 bb = ((const float4*)(smem + SGB_OFF))[k4];
                v.x = lrelu((v.x - sh.x) * sc.x + bb.x, 0.01f);
                v.y = lrelu((v.y - sh.y) * sc.y + bb.y, 0.01f);
                v.z = lrelu((v.z - sh.z) * sc.z + bb.z, 0.01f);
                v.w = lrelu((v.w - sh.w) * sc.w + bb.w, 0.01f);
            }
            __nv_bfloat16 h0 = __float2bfloat16_rn(v.x), h1 = __float2bfloat16_rn(v.y);
            __nv_bfloat16 h2 = __float2bfloat16_rn(v.z), h3 = __float2bfloat16_rn(v.w);
            __nv_bfloat162 hp0; hp0.x = h0; hp0.y = h1;
            __nv_bfloat162 hp1; hp1.x = h2; hp1.y = h3;
            __nv_bfloat162 lp0 = __floats2bfloat162_rn(v.x - __bfloat162float(h0),
                                                       v.y - __bfloat162float(h1));
            __nv_bfloat162 lp1 = __floats2bfloat162_rn(v.z - __bfloat162float(h2),
                                                       v.w - __bfloat162float(h3));
            int k0 = k4 << 2;
            uint2 hv = make_uint2(*(unsigned*)&hp0, *(unsigned*)&hp1);
            uint2 lv = make_uint2(*(unsigned*)&lp0, *(unsigned*)&lp1);
            *(uint2*)(smem + (r * ASTRIDE + k0) * 2) = hv;
            *(uint2*)(smem + (r * ASTRIDE + 128 + k0) * 2) = lv;
        }
        __syncthreads();

        int tn = t + gridDim.x;
        if (tn < NTILES) gemm_prefetch(X, tn << 7, sbase + STAGE_OFF, tid);

        float acc[2][8][4];
        #pragma unroll
        for (int mb = 0; mb < 2; mb++)
            #pragma unroll
            for (int nb = 0; nb < 8; nb++)
                #pragma unroll
                for (int j = 0; j < 4; j++) acc[mb][nb][j] = 0.f;

        #pragma unroll
        for (int kk = 0; kk < 24; kk++) {
            int term = kk >> 3, ks = kk & 7;
            int a_off = ks * 16 + ((term == 1) ? 128 : 0);
            int b_off = ks * 16 + ((term == 2) ? 128 : 0);
            uint32_t af[2][4];
            ldm_x4(af[0], aAddr + a_off * 2);
            ldm_x4(af[1], aAddr + a_off * 2 + 16 * ASTRIDE * 2);
            uint32_t bf[4][4];
            #pragma unroll
            for (int nbp = 0; nbp < 4; nbp++)
                ldm_x4(bf[nbp], bAddr + b_off * 2 + nbp * 16 * ASTRIDE * 2);
            #pragma unroll
            for (int mb = 0; mb < 2; mb++)
                #pragma unroll
                for (int nbp = 0; nbp < 4; nbp++) {
                    mma16816(acc[mb][2 * nbp],     af[mb], &bf[nbp][0]);
                    mma16816(acc[mb][2 * nbp + 1], af[mb], &bf[nbp][2]);
                }
        }

        #pragma unroll
        for (int mb = 0; mb < 2; mb++) {
            int rlo = m0 + mb * 16 + qrow;
            int rhi = rlo + 8;
            float as_lo = 0.f, ad_lo = 0.f, as_hi = 0.f, ad_hi = 0.f;
            #pragma unroll
            for (int nb = 0; nb < 8; nb++) {
                int col = n0 + nb * 8 + qcol;
                float c0 = acc[mb][nb][0], c1 = acc[mb][nb][1];
                float c2 = acc[mb][nb][2], c3 = acc[mb][nb][3];
                float s0 = sAVS[col], s1 = sAVS[col + 1];
                float d0 = sAVD[col], d1 = sAVD[col + 1];
                as_lo += c0 * s0 + c1 * s1;  ad_lo += c0 * d0 + c1 * d1;
                as_hi += c2 * s0 + c3 * s1;  ad_hi += c2 * d0 + c3 * d1;
                if (rlo < nrows) {
                    float2* p = (float2*)(Y + (long long)(row0 + rlo) * HH + col);
                    *p = make_float2(c0, c1);
                }
                if (rhi < nrows) {
                    float2* p = (float2*)(Y + (long long)(row0 + rhi) * HH + col);
                    *p = make_float2(c2, c3);
                }
            }
            #pragma unroll
            for (int o = 1; o < 4; o <<= 1) {
                as_lo += __shfl_xor_sync(0xFFFFFFFFu, as_lo, o);
                ad_lo += __shfl_xor_sync(0xFFFFFFFFu, ad_lo, o);
                as_hi += __shfl_xor_sync(0xFFFFFFFFu, as_hi, o);
                ad_hi += __shfl_xor_sync(0xFFFFFFFFu, ad_hi, o);
            }
            if ((lane & 3) == 0) {
                atomicAdd(&sAS[rlo], as_lo); atomicAdd(&sAD[rlo], ad_lo);
                atomicAdd(&sAS[rhi], as_hi); atomicAdd(&sAD[rhi], ad_hi);
            }
        }
        __syncthreads();
        if (tid < nrows) {
            int r = row0 + tid;
            g_as[r] = sAS[tid]; g_ad[r] = sAD[tid];
        }
    }
}

// ---------------- GAT aggregation + fused column stats -----------------------
// 8 warps/block, NPW consecutive nodes per warp; smem-staged src/alpha.
__global__ void __launch_bounds__(256)
k_gat_agg(const float* __restrict__ hW, float* __restrict__ hout,
          const float* __restrict__ bias, int dostats) {
    __shared__ float s_sum[HH], s_sq[HH];
    __shared__ int s_srcbuf[8][32];
    __shared__ float s_albuf[8][32];
    int tid = threadIdx.x;
    int wid = tid >> 5, lane = tid & 31;
    if (dostats && tid < HH) { s_sum[tid] = 0.f; s_sq[tid] = 0.f; }
    __syncthreads();

    float4 bb = ((const float4*)bias)[lane];
    float4 cs = make_float4(0.f, 0.f, 0.f, 0.f);
    float4 cq = make_float4(0.f, 0.f, 0.f, 0.f);
    int nbase = (blockIdx.x * 8 + wid) * NPW;

    for (int n = 0; n < NPW; n++) {
        int node = nbase + n;
        if (node >= NN) break;
        int rs = g_rowstart[node], re = g_rowstart[node + 1];
        int deg = re - rs;
        float ad_d = g_ad[node];
        float4 acc = bb;

        if (deg <= 32) {
            int my_src = 0;
            float my_logit = -1e30f;
            if (lane < deg) {
                my_src = g_ssrc[rs + lane];
                my_logit = lrelu(g_as[my_src] + ad_d, 0.2f);
            }
            float m = my_logit;
            #pragma unroll
            for (int o = 16; o; o >>= 1) m = fmaxf(m, __shfl_xor_sync(0xFFFFFFFFu, m, o));
            float ex = (lane < deg) ? __expf(my_logit - m) : 0.f;
            float s = ex;
            #pragma unroll
            for (int o = 16; o; o >>= 1) s += __shfl_xor_sync(0xFFFFFFFFu, s, o);
            s_srcbuf[wid][lane] = my_src;
            s_albuf[wid][lane] = ex / (s + 1e-16f);
            __syncwarp();
            #pragma unroll 4
            for (int j = 0; j < deg; j++) {
                int src = s_srcbuf[wid][j];
                float alpha = s_albuf[wid][j];
                float4 v = ((const float4*)(hW + (long long)src * HH))[lane];
                acc.x += alpha * v.x; acc.y += alpha * v.y;
                acc.z += alpha * v.z; acc.w += alpha * v.w;
            }
            __syncwarp();
        } else {
            float m = -1e30f, s = 0.f;
            for (int i = rs + lane; i < re; i += 32) {
                int src = g_ssrc[i];
                float x = lrelu(g_as[src] + ad_d, 0.2f);
                if (x > m) { s = s * __expf(m - x) + 1.f; m = x; }
                else       { s += __expf(x - m); }
            }
            #pragma unroll
            for (int o = 16; o; o >>= 1) {
                float om = __shfl_xor_sync(0xFFFFFFFFu, m, o);
                float os = __shfl_xor_sync(0xFFFFFFFFu, s, o);
                float nm = fmaxf(m, om);
                s = s * __expf(m - nm) + os * __expf(om - nm);
                m = nm;
            }
            float inv = 1.f / (s + 1e-16f);
            for (int i = rs; i < re; ++i) {
                int src = g_ssrc[i];
                float alpha = __expf(lrelu(g_as[src] + ad_d, 0.2f) - m) * inv;
                float4 v = ((const float4*)(hW + (long long)src * HH))[lane];
                acc.x += alpha * v.x; acc.y += alpha * v.y;
                acc.z += alpha * v.z; acc.w += alpha * v.w;
            }
        }
        ((float4*)(hout + (long long)node * HH))[lane] = acc;
        if (dostats) {
            cs.x += acc.x; cs.y += acc.y; cs.z += acc.z; cs.w += acc.w;
            cq.x += acc.x * acc.x; cq.y += acc.y * acc.y;
            cq.z += acc.z * acc.z; cq.w += acc.w * acc.w;
        }
    }

    if (dostats) {
        int c0 = lane << 2;
        atomicAdd(&s_sum[c0],     cs.x); atomicAdd(&s_sum[c0 + 1], cs.y);
        atomicAdd(&s_sum[c0 + 2], cs.z); atomicAdd(&s_sum[c0 + 3], cs.w);
        atomicAdd(&s_sq[c0],      cq.x); atomicAdd(&s_sq[c0 + 1],  cq.y);
        atomicAdd(&s_sq[c0 + 2],  cq.z); atomicAdd(&s_sq[c0 + 3],  cq.w);
        __syncthreads();
        if (tid < HH) {
            atomicAdd(&g_colsum[tid], s_sum[tid]);
            atomicAdd(&g_colsq[tid], s_sq[tid]);
        }
    }
}

// ---------------- GraphNorm prep (self-zeroing stats) ------------------------
__global__ void k_norm_prep(const float* __restrict__ w, const float* __restrict__ b,
                            const float* __restrict__ ms) {
    int c = threadIdx.x;
    if (c >= HH) return;
    float invN = 1.0f / (float)NN;
    float mean = g_colsum[c] * invN;
    float ex2 = g_colsq[c] * invN;
    float s = ms[c];
    float var = ex2 - 2.f * s * mean * mean + s * s * mean * mean;
    g_shift[c] = mean * s;
    g_scale[c] = w[c] * rsqrtf(var + EPSN);
    g_gb[c] = b[c];
    g_colsum[c] = 0.f;       // re-arm for next layer / next graph replay
    g_colsq[c] = 0.f;
}

// ---------------- pooling + MLP ---------------------------------------------
#define PCH 256
__global__ void k_pool2(const float* __restrict__ h) {
    int c = threadIdx.x;
    int r0 = blockIdx.x * PCH;
    int rend = r0 + PCH; if (rend > NN) rend = NN;
    if (r0 >= NN) return;
    int cur = g_batch[r0];
    float acc = 0.f;
    for (int r = r0; r < rend; r++) {
        int b = g_batch[r];
        if (b != cur) { atomicAdd(&g_pool[cur * HH + c], acc); acc = 0.f; cur = b; }
        acc += h[(long long)r * HH + c];
    }
    atomicAdd(&g_pool[cur * HH + c], acc);
}

__global__ void k_mlp1(const float* __restrict__ W1, const float* __restrict__ b1) {
    __shared__ float sp[HH];
    int g = blockIdx.x, c = threadIdx.x;
    sp[c] = g_pool[g * HH + c];
    __syncthreads();
    float acc = b1[c];
    #pragma unroll 4
    for (int k = 0; k < HH; k++) acc += sp[k] * W1[k * HH + c];
    g_z[g * HH + c] = lrelu(acc, 0.01f);
}

__global__ void k_mlp2(const float* __restrict__ W2, const float* __restrict__ b2,
                       float* __restrict__ out) {
    __shared__ float sz[HH];
    int g = blockIdx.x, a = threadIdx.x;
    sz[a] = g_z[g * HH + a];
    sz[a + 64] = g_z[g * HH + a + 64];
    __syncthreads();
    float acc = b2[a];
    #pragma unroll 4
    for (int k = 0; k < HH; k++) acc += sz[k] * W2[k * AA + a];
    out[g * AA + a] = acc;
}

// ---------------- launcher ---------------------------------------------------
extern "C" void kernel_launch(void* const* d_in, const int* in_sizes, int n_in,
                              void* d_out, int out_size) {
    const float* x        = (const float*)d_in[0];
    const void*  e_raw    = d_in[1];
    const void*  b_raw    = d_in[2];
    const float* Ws       = (const float*)d_in[3];
    const float* att_src  = (const float*)d_in[4];
    const float* att_dst  = (const float*)d_in[5];
    const float* conv_bias= (const float*)d_in[6];
    const float* gn_w     = (const float*)d_in[7];
    const float* gn_b     = (const float*)d_in[8];
    const float* gn_ms    = (const float*)d_in[9];
    const float* W1       = (const float*)d_in[10];
    const float* b1       = (const float*)d_in[11];
    const float* W2       = (const float*)d_in[12];
    const float* b2       = (const float*)d_in[13];

    float* bufA; float* bufB;
    cudaGetSymbolAddress((void**)&bufA, g_bufA);
    cudaGetSymbolAddress((void**)&bufB, g_bufB);

    cudaFuncSetAttribute(k_gemm_mma, cudaFuncAttributeMaxDynamicSharedMemorySize, GEMM_SMEM);

    const int eg = (EE + 255) / 256;
    const int ng = (NN + 255) / 256;
    const int NB = (NN + 1023) / 1024;

    k_detect<<<1, 256>>>(e_raw, b_raw);
    k_cvt<<<eg, 256>>>(e_raw, b_raw);
    k_prepW<<<(LL * HH * HH + 255) / 256, 256>>>(Ws);
    k_hist<<<eg, 256>>>();
    k_scan1<<<NB, 256>>>();
    k_scan2<<<1, 128>>>();
    k_scan3<<<ng, 256>>>();
    k_fill<<<eg, 256>>>();

    const int agg_grid = (NN + 8 * NPW - 1) / (8 * NPW);

    for (int l = 0; l < LL; l++) {
        const float* hin = (l == 0) ? x : bufB;
        k_gemm_mma<<<148, 256, GEMM_SMEM>>>(hin, l, bufA,
                                            att_src + l * HH, att_dst + l * HH,
                                            l > 0 ? 1 : 0);
        k_gat_agg<<<agg_grid, 256>>>(bufA, bufB, conv_bias + l * HH,
                                     l < LL - 1 ? 1 : 0);
        if (l < LL - 1) {
            k_norm_prep<<<1, 128>>>(gn_w + l * HH, gn_b + l * HH, gn_ms + l * HH);
        }
    }

    k_pool2<<<(NN + PCH - 1) / PCH, 128>>>(bufB);
    k_mlp1<<<GG, 128>>>(W1, b1);
    k_mlp2<<<GG, 64>>>(W2, b2, (float*)d_out);
}

// round 7
// speedup vs baseline: 2.9075x; 1.3759x over previous
#include <cuda_runtime.h>
#include <cuda_bf16.h>
#include <cstdint>

#define NN 100000
#define EE 600000
#define HH 128
#define AA 64
#define GG 64
#define LL 3
#define EPSN 1e-5f
#define NTILES 782
#define ASTRIDE 264
#define IMG_ELEMS (HH * ASTRIDE)
#define NPW 4

// ---------------- scratch (device globals) ----------------------------------
__device__ float g_bufA[NN * HH];
__device__ float g_bufB[NN * HH];
__device__ float g_as[NN], g_ad[NN];
__device__ int g_src[EE], g_dst[EE];
__device__ int g_batch[NN];
__device__ int g_deg[NN];
__device__ int g_rowstart[NN + 1];
__device__ int g_cursor[NN];
__device__ int g_ssrc[EE];
__device__ int g_bsum[128], g_boff[128];
__device__ float g_colsum[HH], g_colsq[HH];
__device__ float g_shift[HH], g_scale[HH], g_gb[HH];
__device__ float g_pool[GG * HH];
__device__ int g_edge_is32, g_batch_is32;
__device__ __align__(16) __nv_bfloat16 g_Wimg[LL * IMG_ELEMS];

__device__ __forceinline__ float lrelu(float x, float a) { return x > 0.f ? x : a * x; }

__device__ __forceinline__ uint32_t smem_u32(const void* p) {
    uint32_t a;
    asm("{ .reg .u64 t; cvta.to.shared.u64 t, %1; cvt.u32.u64 %0, t; }" : "=r"(a) : "l"(p));
    return a;
}
__device__ __forceinline__ void ldm_x4(uint32_t* r, uint32_t addr) {
    asm volatile("ldmatrix.sync.aligned.m8n8.x4.shared.b16 {%0,%1,%2,%3}, [%4];"
                 : "=r"(r[0]), "=r"(r[1]), "=r"(r[2]), "=r"(r[3]) : "r"(addr));
}
__device__ __forceinline__ void mma16816(float* c, const uint32_t* a, const uint32_t* b) {
    asm volatile("mma.sync.aligned.m16n8k16.row.col.f32.bf16.bf16.f32 "
                 "{%0,%1,%2,%3}, {%4,%5,%6,%7}, {%8,%9}, {%0,%1,%2,%3};"
                 : "+f"(c[0]), "+f"(c[1]), "+f"(c[2]), "+f"(c[3])
                 : "r"(a[0]), "r"(a[1]), "r"(a[2]), "r"(a[3]), "r"(b[0]), "r"(b[1]));
}
__device__ __forceinline__ void cpa16(uint32_t dst, const void* src, int sz) {
    asm volatile("cp.async.cg.shared.global [%0], [%1], 16, %2;"
                 :: "r"(dst), "l"(src), "r"(sz) : "memory");
}
#define CPA_COMMIT() asm volatile("cp.async.commit_group;" ::: "memory")
#define CPA_WAIT0()  asm volatile("cp.async.wait_group 0;" ::: "memory")
__device__ __forceinline__ void red4(float* p, float4 v) {
    asm volatile("red.global.add.v4.f32 [%0], {%1,%2,%3,%4};"
                 :: "l"(p), "f"(v.x), "f"(v.y), "f"(v.z), "f"(v.w) : "memory");
}

// ---------------- dtype detection ------------------------------------------
__global__ void k_detect(const void* eraw, const void* braw) {
    __shared__ int s_e, s_b;
    if (threadIdx.x == 0) { s_e = 0; s_b = 0; }
    __syncthreads();
    const long long* e64 = (const long long*)eraw;
    const long long* b64 = (const long long*)braw;
    int bad_e = 0, bad_b = 0;
    for (int i = threadIdx.x; i < 1024; i += blockDim.x) {
        long long v = e64[(long long)i * (EE / 1024)];
        if (v < 0 || v >= NN) bad_e = 1;
        long long bv = b64[(long long)i * ((NN / 2) / 1024)];
        if (bv < 0 || bv >= GG) bad_b = 1;
    }
    if (bad_e) atomicOr(&s_e, 1);
    if (bad_b) atomicOr(&s_b, 1);
    __syncthreads();
    if (threadIdx.x == 0) { g_edge_is32 = s_e; g_batch_is32 = s_b; }
}

// cvt + histogram fused.  g_deg starts 0 (static init / re-zeroed by k_scan3).
__global__ void k_cvt(const void* eraw, const void* braw) {
    int i = blockIdx.x * blockDim.x + threadIdx.x;
    if (i < EE) {
        int s, d;
        if (g_edge_is32) {
            const int* p = (const int*)eraw;
            s = p[i]; d = p[EE + i];
        } else {
            const long long* p = (const long long*)eraw;
            s = (int)p[i]; d = (int)p[EE + i];
        }
        g_src[i] = s; g_dst[i] = d;
        atomicAdd(&g_deg[d], 1);
    }
    if (i < NN) {
        if (g_batch_is32) g_batch[i] = ((const int*)braw)[i];
        else              g_batch[i] = (int)((const long long*)braw)[i];
    }
    if (i < GG * HH) g_pool[i] = 0.f;
}

// ---------------- W prep ----------------------------------------------------
__global__ void k_prepW(const float* __restrict__ Ws) {
    int i = blockIdx.x * blockDim.x + threadIdx.x;
    if (i >= LL * HH * HH) return;
    int l = i / (HH * HH);
    int r = i - l * HH * HH;
    int k = r >> 7;
    int n = r & 127;
    float w = Ws[i];
    __nv_bfloat16 hi = __float2bfloat16_rn(w);
    float resid = w - __bfloat162float(hi);
    __nv_bfloat16 lo = __float2bfloat16_rn(resid);
    __nv_bfloat16* img = g_Wimg + (long long)l * IMG_ELEMS;
    img[n * ASTRIDE + k] = hi;
    img[n * ASTRIDE + 128 + k] = lo;
}

// ---------------- CSR build -------------------------------------------------
__global__ void k_scan1() {
    __shared__ int s_w[8];
    int b = blockIdx.x, t = threadIdx.x;
    int base = b * 1024 + t * 4;
    int d[4];
    #pragma unroll
    for (int i = 0; i < 4; i++) d[i] = (base + i < NN) ? g_deg[base + i] : 0;
    int local = d[0] + d[1] + d[2] + d[3];
    int lane = t & 31, w = t >> 5;
    int v = local;
    #pragma unroll
    for (int o = 1; o < 32; o <<= 1) {
        int u = __shfl_up_sync(0xFFFFFFFFu, v, o);
        if (lane >= o) v += u;
    }
    if (lane == 31) s_w[w] = v;
    __syncthreads();
    if (t < 8) {
        int x = s_w[t];
        #pragma unroll
        for (int o = 1; o < 8; o <<= 1) {
            int u = __shfl_up_sync(0xFFu, x, o);
            if (t >= o) x += u;
        }
        s_w[t] = x;
    }
    __syncthreads();
    int warpoff = (w > 0) ? s_w[w - 1] : 0;
    int excl = warpoff + v - local;
    #pragma unroll
    for (int i = 0; i < 4; i++) {
        if (base + i < NN) g_rowstart[base + i] = excl;
        excl += d[i];
    }
    if (t == 0) g_bsum[b] = s_w[7];
}

__global__ void k_scan2() {
    __shared__ int sb[128];
    int t = threadIdx.x;
    int NB = (NN + 1023) / 1024;
    sb[t] = (t < NB) ? g_bsum[t] : 0;
    __syncthreads();
    for (int o = 1; o < 128; o <<= 1) {
        int u = (t >= o) ? sb[t - o] : 0;
        __syncthreads();
        sb[t] += u;
        __syncthreads();
    }
    g_boff[t] = (t > 0) ? sb[t - 1] : 0;
}

__global__ void k_scan3() {
    int i = blockIdx.x * blockDim.x + threadIdx.x;
    if (i < NN) {
        int v = g_rowstart[i] + g_boff[i >> 10];
        g_rowstart[i] = v;
        g_cursor[i] = v;
        g_deg[i] = 0;      // re-arm histogram for next graph replay
    }
    if (i == 0) g_rowstart[NN] = EE;
}

__global__ void k_fill() {
    int e = blockIdx.x * blockDim.x + threadIdx.x;
    if (e >= EE) return;
    int d = g_dst[e];
    int slot = atomicAdd(&g_cursor[d], 1);
    g_ssrc[slot] = g_src[e];
}

// ---------------- HMMA GEMM: persistent, cp.async pipelined ------------------
#define SA_BYTES  (HH * ASTRIDE * 2)
#define SB_OFF    SA_BYTES
#define STAGE_OFF (2 * SA_BYTES)
#define VEC_OFF   (STAGE_OFF + 65536)
#define SAS_OFF   (VEC_OFF)
#define SAD_OFF   (VEC_OFF + 512)
#define SAVS_OFF  (VEC_OFF + 1024)
#define SAVD_OFF  (VEC_OFF + 1536)
#define SSH_OFF   (VEC_OFF + 2048)
#define SSC_OFF   (VEC_OFF + 2560)
#define SGB_OFF   (VEC_OFF + 3072)
#define GEMM_SMEM (VEC_OFF + 3584)

__device__ __forceinline__ void gemm_prefetch(const float* __restrict__ X, int row0,
                                              uint32_t stage, int tid) {
    int nrows = NN - row0; if (nrows > 128) nrows = 128;
    #pragma unroll
    for (int i = 0; i < 16; i++) {
        int c = i * 256 + tid;
        int r = c >> 5, k4 = c & 31;
        int rr = r < nrows ? r : 0;
        const float4* src = ((const float4*)(X + (long long)(row0 + rr) * HH)) + k4;
        cpa16(stage + c * 16, src, r < nrows ? 16 : 0);
    }
    CPA_COMMIT();
}

__global__ void __launch_bounds__(256, 1)
k_gemm_mma(const float* __restrict__ X, int layer, float* __restrict__ Y,
           const float* __restrict__ avs, const float* __restrict__ avd,
           int donorm) {
    extern __shared__ char smem[];
    uint32_t sbase = smem_u32(smem);
    int tid = threadIdx.x;
    int wid = tid >> 5, lane = tid & 31;

    float* sAS = (float*)(smem + SAS_OFF);
    float* sAD = (float*)(smem + SAD_OFF);
    float* sAVS = (float*)(smem + SAVS_OFF);
    float* sAVD = (float*)(smem + SAVD_OFF);

    if (tid < 128) {
        sAVS[tid] = avs[tid];
        sAVD[tid] = avd[tid];
        if (donorm) {
            ((float*)(smem + SSH_OFF))[tid] = g_shift[tid];
            ((float*)(smem + SSC_OFF))[tid] = g_scale[tid];
            ((float*)(smem + SGB_OFF))[tid] = g_gb[tid];
        }
    }
    {
        const float4* src = (const float4*)(g_Wimg + (long long)layer * IMG_ELEMS);
        float4* dst = (float4*)(smem + SB_OFF);
        for (int i = tid; i < 4224; i += 256) dst[i] = src[i];
    }

    int m0 = (wid >> 1) << 5;
    int n0 = (wid & 1) << 6;
    int arow = m0 + (lane & 7) + ((lane >> 3) & 1) * 8;
    uint32_t aAddr = sbase + (arow * ASTRIDE + ((lane >> 4) & 1) * 8) * 2;
    int brow = n0 + (lane & 7) + ((lane >> 4) & 1) * 8;
    uint32_t bAddr = sbase + SB_OFF + (brow * ASTRIDE + ((lane >> 3) & 1) * 8) * 2;
    int qrow = lane >> 2;
    int qcol = (lane & 3) << 1;

    int t0 = blockIdx.x;
    if (t0 < NTILES) gemm_prefetch(X, t0 << 7, sbase + STAGE_OFF, tid);

    for (int t = t0; t < NTILES; t += gridDim.x) {
        int row0 = t << 7;
        int nrows = NN - row0; if (nrows > 128) nrows = 128;
        CPA_WAIT0();
        __syncthreads();

        if (tid < 128) { sAS[tid] = 0.f; sAD[tid] = 0.f; }
        #pragma unroll 4
        for (int i = 0; i < 16; i++) {
            int c = i * 256 + tid;
            int r = c >> 5, k4 = c & 31;
            float4 v = ((const float4*)(smem + STAGE_OFF))[c];
            if (donorm && r < nrows) {
                float4 sh = ((const float4*)(smem + SSH_OFF))[k4];
                float4 sc = ((const float4*)(smem + SSC_OFF))[k4];
                float4 bb = ((const float4*)(smem + SGB_OFF))[k4];
                v.x = lrelu((v.x - sh.x) * sc.x + bb.x, 0.01f);
                v.y = lrelu((v.y - sh.y) * sc.y + bb.y, 0.01f);
                v.z = lrelu((v.z - sh.z) * sc.z + bb.z, 0.01f);
                v.w = lrelu((v.w - sh.w) * sc.w + bb.w, 0.01f);
            }
            __nv_bfloat16 h0 = __float2bfloat16_rn(v.x), h1 = __float2bfloat16_rn(v.y);
            __nv_bfloat16 h2 = __float2bfloat16_rn(v.z), h3 = __float2bfloat16_rn(v.w);
            __nv_bfloat162 hp0; hp0.x = h0; hp0.y = h1;
            __nv_bfloat162 hp1; hp1.x = h2; hp1.y = h3;
            __nv_bfloat162 lp0 = __floats2bfloat162_rn(v.x - __bfloat162float(h0),
                                                       v.y - __bfloat162float(h1));
            __nv_bfloat162 lp1 = __floats2bfloat162_rn(v.z - __bfloat162float(h2),
                                                       v.w - __bfloat162float(h3));
            int k0 = k4 << 2;
            uint2 hv = make_uint2(*(unsigned*)&hp0, *(unsigned*)&hp1);
            uint2 lv = make_uint2(*(unsigned*)&lp0, *(unsigned*)&lp1);
            *(uint2*)(smem + (r * ASTRIDE + k0) * 2) = hv;
            *(uint2*)(smem + (r * ASTRIDE + 128 + k0) * 2) = lv;
        }
        __syncthreads();

        int tn = t + gridDim.x;
        if (tn < NTILES) gemm_prefetch(X, tn << 7, sbase + STAGE_OFF, tid);

        float acc[2][8][4];
        #pragma unroll
        for (int mb = 0; mb < 2; mb++)
            #pragma unroll
            for (int nb = 0; nb < 8; nb++)
                #pragma unroll
                for (int j = 0; j < 4; j++) acc[mb][nb][j] = 0.f;

        // ks-shared fragments: per ks load Ah,Al once, Bh,Bl per nbp;
        // terms: Xh*Wh + Xl*Wh + Xh*Wl
        #pragma unroll
        for (int ks = 0; ks < 8; ks++) {
            int kofs = ks * 16;
            uint32_t ah[2][4], al[2][4];
            ldm_x4(ah[0], aAddr + kofs * 2);
            ldm_x4(ah[1], aAddr + kofs * 2 + 16 * ASTRIDE * 2);
            ldm_x4(al[0], aAddr + (kofs + 128) * 2);
            ldm_x4(al[1], aAddr + (kofs + 128) * 2 + 16 * ASTRIDE * 2);
            #pragma unroll
            for (int nbp = 0; nbp < 4; nbp++) {
                uint32_t bh[4], bl[4];
                ldm_x4(bh, bAddr + kofs * 2 + nbp * 16 * ASTRIDE * 2);
                ldm_x4(bl, bAddr + (kofs + 128) * 2 + nbp * 16 * ASTRIDE * 2);
                #pragma unroll
                for (int mb = 0; mb < 2; mb++) {
                    mma16816(acc[mb][2 * nbp],     ah[mb], &bh[0]);
                    mma16816(acc[mb][2 * nbp + 1], ah[mb], &bh[2]);
                    mma16816(acc[mb][2 * nbp],     al[mb], &bh[0]);
                    mma16816(acc[mb][2 * nbp + 1], al[mb], &bh[2]);
                    mma16816(acc[mb][2 * nbp],     ah[mb], &bl[0]);
                    mma16816(acc[mb][2 * nbp + 1], ah[mb], &bl[2]);
                }
            }
        }

        #pragma unroll
        for (int mb = 0; mb < 2; mb++) {
            int rlo = m0 + mb * 16 + qrow;
            int rhi = rlo + 8;
            float as_lo = 0.f, ad_lo = 0.f, as_hi = 0.f, ad_hi = 0.f;
            #pragma unroll
            for (int nb = 0; nb < 8; nb++) {
                int col = n0 + nb * 8 + qcol;
                float c0 = acc[mb][nb][0], c1 = acc[mb][nb][1];
                float c2 = acc[mb][nb][2], c3 = acc[mb][nb][3];
                float s0 = sAVS[col], s1 = sAVS[col + 1];
                float d0 = sAVD[col], d1 = sAVD[col + 1];
                as_lo += c0 * s0 + c1 * s1;  ad_lo += c0 * d0 + c1 * d1;
                as_hi += c2 * s0 + c3 * s1;  ad_hi += c2 * d0 + c3 * d1;
                if (rlo < nrows) {
                    float2* p = (float2*)(Y + (long long)(row0 + rlo) * HH + col);
                    *p = make_float2(c0, c1);
                }
                if (rhi < nrows) {
                    float2* p = (float2*)(Y + (long long)(row0 + rhi) * HH + col);
                    *p = make_float2(c2, c3);
                }
            }
            #pragma unroll
            for (int o = 1; o < 4; o <<= 1) {
                as_lo += __shfl_xor_sync(0xFFFFFFFFu, as_lo, o);
                ad_lo += __shfl_xor_sync(0xFFFFFFFFu, ad_lo, o);
                as_hi += __shfl_xor_sync(0xFFFFFFFFu, as_hi, o);
                ad_hi += __shfl_xor_sync(0xFFFFFFFFu, ad_hi, o);
            }
            if ((lane & 3) == 0) {
                atomicAdd(&sAS[rlo], as_lo); atomicAdd(&sAD[rlo], ad_lo);
                atomicAdd(&sAS[rhi], as_hi); atomicAdd(&sAD[rhi], ad_hi);
            }
        }
        __syncthreads();
        if (tid < nrows) {
            int r = row0 + tid;
            g_as[r] = sAS[tid]; g_ad[r] = sAD[tid];
        }
    }
}

// ---------------- GAT aggregation + fused stats / pooling --------------------
// mode: 0 = plain, 1 = +column stats (GraphNorm), 2 = +global_add_pool (last
// layer; skips the hout store entirely).
__global__ void __launch_bounds__(256)
k_gat_agg(const float* __restrict__ hW, float* __restrict__ hout,
          const float* __restrict__ bias, int mode) {
    __shared__ float s_sum[HH], s_sq[HH];
    __shared__ int s_srcbuf[8][32];
    __shared__ float s_albuf[8][32];
    int tid = threadIdx.x;
    int wid = tid >> 5, lane = tid & 31;
    if (mode == 1 && tid < HH) { s_sum[tid] = 0.f; s_sq[tid] = 0.f; }
    __syncthreads();

    float4 bb = ((const float4*)bias)[lane];
    float4 cs = make_float4(0.f, 0.f, 0.f, 0.f);
    float4 cq = make_float4(0.f, 0.f, 0.f, 0.f);
    float4 pacc = make_float4(0.f, 0.f, 0.f, 0.f);
    int curb = -1;
    int nbase = (blockIdx.x * 8 + wid) * NPW;

    for (int n = 0; n < NPW; n++) {
        int node = nbase + n;
        if (node >= NN) break;
        int rs = g_rowstart[node], re = g_rowstart[node + 1];
        int deg = re - rs;
        float ad_d = g_ad[node];
        float4 acc = bb;

        if (deg <= 32) {
            // shift-invariant softmax: logits bounded (~|6|), exp safe in fp32
            int my_src = 0;
            float ex = 0.f;
            if (lane < deg) {
                my_src = g_ssrc[rs + lane];
                ex = __expf(lrelu(g_as[my_src] + ad_d, 0.2f));
            }
            float s = ex;
            #pragma unroll
            for (int o = 16; o; o >>= 1) s += __shfl_xor_sync(0xFFFFFFFFu, s, o);
            s_srcbuf[wid][lane] = my_src;
            s_albuf[wid][lane] = ex / (s + 1e-16f);
            __syncwarp();
            #pragma unroll 4
            for (int j = 0; j < deg; j++) {
                int src = s_srcbuf[wid][j];
                float alpha = s_albuf[wid][j];
                float4 v = ((const float4*)(hW + (long long)src * HH))[lane];
                acc.x += alpha * v.x; acc.y += alpha * v.y;
                acc.z += alpha * v.z; acc.w += alpha * v.w;
            }
            __syncwarp();
        } else {
            float m = -1e30f, s = 0.f;
            for (int i = rs + lane; i < re; i += 32) {
                int src = g_ssrc[i];
                float x = lrelu(g_as[src] + ad_d, 0.2f);
                if (x > m) { s = s * __expf(m - x) + 1.f; m = x; }
                else       { s += __expf(x - m); }
            }
            #pragma unroll
            for (int o = 16; o; o >>= 1) {
                float om = __shfl_xor_sync(0xFFFFFFFFu, m, o);
                float os = __shfl_xor_sync(0xFFFFFFFFu, s, o);
                float nm = fmaxf(m, om);
                s = s * __expf(m - nm) + os * __expf(om - nm);
                m = nm;
            }
            float inv = 1.f / (s + 1e-16f);
            for (int i = rs; i < re; ++i) {
                int src = g_ssrc[i];
                float alpha = __expf(lrelu(g_as[src] + ad_d, 0.2f) - m) * inv;
                float4 v = ((const float4*)(hW + (long long)src * HH))[lane];
                acc.x += alpha * v.x; acc.y += alpha * v.y;
                acc.z += alpha * v.z; acc.w += alpha * v.w;
            }
        }

        if (mode == 2) {
            int b = g_batch[node];
            if (b != curb) {
                if (curb >= 0) red4(&g_pool[curb * HH + (lane << 2)], pacc);
                curb = b;
                pacc = make_float4(0.f, 0.f, 0.f, 0.f);
            }
            pacc.x += acc.x; pacc.y += acc.y; pacc.z += acc.z; pacc.w += acc.w;
        } else {
            ((float4*)(hout + (long long)node * HH))[lane] = acc;
            if (mode == 1) {
                cs.x += acc.x; cs.y += acc.y; cs.z += acc.z; cs.w += acc.w;
                cq.x += acc.x * acc.x; cq.y += acc.y * acc.y;
                cq.z += acc.z * acc.z; cq.w += acc.w * acc.w;
            }
        }
    }

    if (mode == 2) {
        if (curb >= 0) red4(&g_pool[curb * HH + (lane << 2)], pacc);
    } else if (mode == 1) {
        int c0 = lane << 2;
        atomicAdd(&s_sum[c0],     cs.x); atomicAdd(&s_sum[c0 + 1], cs.y);
        atomicAdd(&s_sum[c0 + 2], cs.z); atomicAdd(&s_sum[c0 + 3], cs.w);
        atomicAdd(&s_sq[c0],      cq.x); atomicAdd(&s_sq[c0 + 1],  cq.y);
        atomicAdd(&s_sq[c0 + 2],  cq.z); atomicAdd(&s_sq[c0 + 3],  cq.w);
        __syncthreads();
        if (tid < HH) {
            atomicAdd(&g_colsum[tid], s_sum[tid]);
            atomicAdd(&g_colsq[tid], s_sq[tid]);
        }
    }
}

// ---------------- GraphNorm prep (self-zeroing stats) ------------------------
__global__ void k_norm_prep(const float* __restrict__ w, const float* __restrict__ b,
                            const float* __restrict__ ms) {
    int c = threadIdx.x;
    if (c >= HH) return;
    float invN = 1.0f / (float)NN;
    float mean = g_colsum[c] * invN;
    float ex2 = g_colsq[c] * invN;
    float s = ms[c];
    float var = ex2 - 2.f * s * mean * mean + s * s * mean * mean;
    g_shift[c] = mean * s;
    g_scale[c] = w[c] * rsqrtf(var + EPSN);
    g_gb[c] = b[c];
    g_colsum[c] = 0.f;
    g_colsq[c] = 0.f;
}

// ---------------- fused MLP ---------------------------------------------------
__global__ void k_mlp(const float* __restrict__ W1, const float* __restrict__ b1,
                      const float* __restrict__ W2, const float* __restrict__ b2,
                      float* __restrict__ out) {
    __shared__ float sp[HH], sz[HH];
    int g = blockIdx.x, c = threadIdx.x;
    sp[c] = g_pool[g * HH + c];
    __syncthreads();
    float a1 = b1[c];
    #pragma unroll 4
    for (int k = 0; k < HH; k++) a1 += sp[k] * W1[k * HH + c];
    sz[c] = lrelu(a1, 0.01f);
    __syncthreads();
    if (c < AA) {
        float a2 = b2[c];
        #pragma unroll 4
        for (int k = 0; k < HH; k++) a2 += sz[k] * W2[k * AA + c];
        out[g * AA + c] = a2;
    }
}

// ---------------- launcher ---------------------------------------------------
extern "C" void kernel_launch(void* const* d_in, const int* in_sizes, int n_in,
                              void* d_out, int out_size) {
    const float* x        = (const float*)d_in[0];
    const void*  e_raw    = d_in[1];
    const void*  b_raw    = d_in[2];
    const float* Ws       = (const float*)d_in[3];
    const float* att_src  = (const float*)d_in[4];
    const float* att_dst  = (const float*)d_in[5];
    const float* conv_bias= (const float*)d_in[6];
    const float* gn_w     = (const float*)d_in[7];
    const float* gn_b     = (const float*)d_in[8];
    const float* gn_ms    = (const float*)d_in[9];
    const float* W1       = (const float*)d_in[10];
    const float* b1       = (const float*)d_in[11];
    const float* W2       = (const float*)d_in[12];
    const float* b2       = (const float*)d_in[13];

    float* bufA; float* bufB;
    cudaGetSymbolAddress((void**)&bufA, g_bufA);
    cudaGetSymbolAddress((void**)&bufB, g_bufB);

    cudaFuncSetAttribute(k_gemm_mma, cudaFuncAttributeMaxDynamicSharedMemorySize, GEMM_SMEM);

    const int eg = (EE + 255) / 256;
    const int ng = (NN + 255) / 256;
    const int NB = (NN + 1023) / 1024;

    k_detect<<<1, 256>>>(e_raw, b_raw);
    k_cvt<<<eg, 256>>>(e_raw, b_raw);
    k_prepW<<<(LL * HH * HH + 255) / 256, 256>>>(Ws);
    k_scan1<<<NB, 256>>>();
    k_scan2<<<1, 128>>>();
    k_scan3<<<ng, 256>>>();
    k_fill<<<eg, 256>>>();

    const int agg_grid = (NN + 8 * NPW - 1) / (8 * NPW);

    for (int l = 0; l < LL; l++) {
        const float* hin = (l == 0) ? x : bufB;
        k_gemm_mma<<<148, 256, GEMM_SMEM>>>(hin, l, bufA,
                                            att_src + l * HH, att_dst + l * HH,
                                            l > 0 ? 1 : 0);
        int mode = (l < LL - 1) ? 1 : 2;
        k_gat_agg<<<agg_grid, 256>>>(bufA, bufB, conv_bias + l * HH, mode);
        if (l < LL - 1) {
            k_norm_prep<<<1, 128>>>(gn_w + l * HH, gn_b + l * HH, gn_ms + l * HH);
        }
    }

    k_mlp<<<GG, 128>>>(W1, b1, W2, b2, (float*)d_out);
}